// round 5
// baseline (speedup 1.0000x reference)
#include <cuda_runtime.h>
#include <cuda_fp16.h>
#include <math_constants.h>
#include <cstdint>

#define B_ 8
#define C_ 128
#define N_ 2304
#define BM 128
#define BN 64

// ---------------- attention smem strides (halfs) ----------------
#define SQh 136
#define SKh 136
#define SVh 72
#define OFF_Q 0
#define OFF_K (BM*SQh)                    // 17408
#define OFF_V (OFF_K + 2*BN*SKh)          // 34816
#define SMEM_HALFS (OFF_V + 2*C_*SVh)     // 53248 halfs = 106496 B

// ---------------- qkv smem strides (halfs) ----------------
#define SX 136
#define SW 136
#define ST 136
#define QOFF_X  0
#define QOFF_W0 (C_*SX)
#define QOFF_W1 (QOFF_W0 + C_*SW)
#define QOFF_T  (QOFF_W1 + C_*SW)
#define QKV_SMEM_HALFS (QOFF_T + C_*ST)

__device__ __half g_qh[B_*N_*C_];   // [b][n][c]
__device__ __half g_kh[B_*N_*C_];   // [b][n][c]
__device__ __half g_vh[B_*C_*N_];   // [b][c][n]
__device__ __half g_xh[B_*C_*N_];   // [b][c][n]
__device__ __half g_wh[3*C_*C_];    // [which][o][c]
__device__ float  g_se[B_*C_];

// ---------------------------------------------------------------------------
__device__ __forceinline__ void cpa16(uint32_t s, const void* g){
    asm volatile("cp.async.cg.shared.global [%0], [%1], 16;" :: "r"(s), "l"(g));
}
__device__ __forceinline__ void cp_commit(){ asm volatile("cp.async.commit_group;"); }
__device__ __forceinline__ void cp_wait0(){ asm volatile("cp.async.wait_group 0;"); }

__device__ __forceinline__ void ldsm4(uint32_t& r0,uint32_t& r1,uint32_t& r2,uint32_t& r3,
                                      uint32_t a){
    asm volatile("ldmatrix.sync.aligned.m8n8.x4.shared.b16 {%0,%1,%2,%3}, [%4];"
        : "=r"(r0),"=r"(r1),"=r"(r2),"=r"(r3) : "r"(a));
}
__device__ __forceinline__ void ldsm4t(uint32_t& r0,uint32_t& r1,uint32_t& r2,uint32_t& r3,
                                       uint32_t a){
    asm volatile("ldmatrix.sync.aligned.m8n8.x4.trans.shared.b16 {%0,%1,%2,%3}, [%4];"
        : "=r"(r0),"=r"(r1),"=r"(r2),"=r"(r3) : "r"(a));
}
__device__ __forceinline__ void sts32(uint32_t a, uint32_t v){
    asm volatile("st.shared.b32 [%0], %1;" :: "r"(a), "r"(v));
}
__device__ __forceinline__ void mma16(float* d, uint32_t a0,uint32_t a1,uint32_t a2,uint32_t a3,
                                      uint32_t b0,uint32_t b1){
    asm volatile(
      "mma.sync.aligned.m16n8k16.row.col.f32.f16.f16.f32 "
      "{%0,%1,%2,%3}, {%4,%5,%6,%7}, {%8,%9}, {%0,%1,%2,%3};"
      : "+f"(d[0]), "+f"(d[1]), "+f"(d[2]), "+f"(d[3])
      : "r"(a0), "r"(a1), "r"(a2), "r"(a3), "r"(b0), "r"(b1));
}
__device__ __forceinline__ uint32_t h2u(__half2 h){ return *reinterpret_cast<uint32_t*>(&h); }

// ---------------------------------------------------------------------------
// prep: fp32 -> fp16 for x and the 3 weight matrices
// ---------------------------------------------------------------------------
#define X2_TOTAL (B_*C_*N_/2)
#define W2_TOTAL (3*C_*C_/2)
__global__ __launch_bounds__(256) void prep_kernel(
    const float* __restrict__ x,
    const float* __restrict__ Wq,
    const float* __restrict__ Wk,
    const float* __restrict__ Wv)
{
    int idx = blockIdx.x * 256 + threadIdx.x;
    if (idx < X2_TOTAL) {
        float2 v = ((const float2*)x)[idx];
        ((__half2*)g_xh)[idx] = __floats2half2_rn(v.x, v.y);
    } else if (idx < X2_TOTAL + W2_TOTAL) {
        int wi = idx - X2_TOTAL;
        int which = wi / (C_*C_/2);
        int r = wi - which * (C_*C_/2);
        const float* Wm = (which == 0) ? Wq : (which == 1) ? Wk : Wv;
        float2 v = ((const float2*)Wm)[r];
        ((__half2*)g_wh)[wi] = __floats2half2_rn(v.x, v.y);
    }
}

// ---------------------------------------------------------------------------
// QKV via fp16 tensor cores. grid (N/128, B), block 256 (8 warps).
// ---------------------------------------------------------------------------
__global__ void __launch_bounds__(256, 1) qkv_mma_kernel(
    const float* __restrict__ bq,
    const float* __restrict__ bk,
    const float* __restrict__ bv)
{
    extern __shared__ __half smh[];
    uint32_t sb = (uint32_t)__cvta_generic_to_shared(smh);

    const int tid  = threadIdx.x;
    const int b    = blockIdx.y;
    const int n0   = blockIdx.x * 128;
    const int warp = tid >> 5, lane = tid & 31;
    const int quad = lane >> 2, qt = lane & 3;

    const __half* xb = g_xh + (size_t)b * C_ * N_;

    #pragma unroll
    for (int c2 = 0; c2 < 8; c2++) {
        int ch = tid + c2*256;
        int c = ch >> 4, nb = ch & 15;
        cpa16(sb + 2u*(QOFF_X + c*SX + nb*8), xb + (size_t)c*N_ + n0 + nb*8);
    }
    #pragma unroll
    for (int c2 = 0; c2 < 8; c2++) {
        int ch = tid + c2*256;
        int o = ch >> 4, cb = ch & 15;
        cpa16(sb + 2u*(QOFF_W0 + o*SW + cb*8), g_wh + o*C_ + cb*8);
    }
    cp_commit();
    cp_wait0();
    __syncthreads();

    #pragma unroll
    for (int c2 = 0; c2 < 8; c2++) {
        int ch = tid + c2*256;
        int o = ch >> 4, cb = ch & 15;
        cpa16(sb + 2u*(QOFF_W1 + o*SW + cb*8), g_wh + C_*C_ + o*C_ + cb*8);
    }
    cp_commit();

    const int r16 = lane & 15;
    const int hi8 = (lane >> 4) * 8;
    const uint32_t bX = sb + 2u*(QOFF_X + r16*SX + hi8);
    const uint32_t tst0 = sb + 2u*(QOFF_T + (warp*16 + quad)*ST + qt*2);
    const uint32_t tst1 = tst0 + 2u*8*ST;

    const int o_r0 = warp*16 + quad, o_r1 = o_r0 + 8;

    #pragma unroll
    for (int which = 0; which < 3; which++) {
        const uint32_t wbuf = sb + 2u*((which & 1) ? QOFF_W1 : QOFF_W0);
        const uint32_t aW = wbuf + 2u*((warp*16 + r16)*SW + hi8);

        float acc[16][4];
        #pragma unroll
        for (int nt = 0; nt < 16; nt++)
            #pragma unroll
            for (int r = 0; r < 4; r++) acc[nt][r] = 0.f;

        #pragma unroll
        for (int kc = 0; kc < 8; kc++) {
            uint32_t a0,a1,a2,a3;
            ldsm4(a0,a1,a2,a3, aW + 32u*kc);
            #pragma unroll
            for (int nt16 = 0; nt16 < 8; nt16++) {
                uint32_t b0,b1,b2,b3;
                ldsm4t(b0,b1,b2,b3, bX + 2u*(kc*16*SX + nt16*16));
                mma16(acc[2*nt16],   a0,a1,a2,a3, b0,b1);
                mma16(acc[2*nt16+1], a0,a1,a2,a3, b2,b3);
            }
        }

        const float* bias = (which == 0) ? bq : (which == 1) ? bk : bv;
        float b0f = bias[o_r0], b1f = bias[o_r1];
        #pragma unroll
        for (int nt = 0; nt < 16; nt++) {
            sts32(tst0 + 16u*nt, h2u(__floats2half2_rn(acc[nt][0] + b0f, acc[nt][1] + b0f)));
            sts32(tst1 + 16u*nt, h2u(__floats2half2_rn(acc[nt][2] + b1f, acc[nt][3] + b1f)));
        }
        __syncthreads();

        if (which == 0) {
            #pragma unroll
            for (int c2 = 0; c2 < 8; c2++) {
                int ch = tid + c2*256;
                int o = ch >> 4, cb = ch & 15;
                cpa16(sb + 2u*(QOFF_W0 + o*SW + cb*8), g_wh + 2*C_*C_ + o*C_ + cb*8);
            }
            cp_commit();
        }

        if (which < 2) {
            __half* dsth = (which == 0) ? g_qh : g_kh;
            #pragma unroll
            for (int c2 = 0; c2 < 8; c2++) {
                int ch = tid + c2*256;
                int n = ch >> 4, ob = ch & 15;
                __half tmp[8];
                #pragma unroll
                for (int u = 0; u < 8; u++) tmp[u] = smh[QOFF_T + (ob*8 + u)*ST + n];
                *(uint4*)(dsth + ((size_t)b*N_ + n0 + n)*C_ + ob*8) = *(uint4*)tmp;
            }
        } else {
            #pragma unroll
            for (int c2 = 0; c2 < 8; c2++) {
                int ch = tid + c2*256;
                int o = ch >> 4, nb = ch & 15;
                uint4 v = *(uint4*)&smh[QOFF_T + o*ST + nb*8];
                *(uint4*)(g_vh + ((size_t)b*C_ + o)*N_ + n0 + nb*8) = v;
            }
        }

        if (which < 2) { cp_wait0(); }
        __syncthreads();
    }
}

// ---------------------------------------------------------------------------
// SE branch
// ---------------------------------------------------------------------------
__global__ __launch_bounds__(256) void se_kernel(
    const float* __restrict__ x,
    const float* __restrict__ w1,
    const float* __restrict__ w2)
{
    __shared__ float y[C_];
    __shared__ float y1[C_/16];
    int b = blockIdx.x;
    int tid = threadIdx.x;
    int warp = tid >> 5, lane = tid & 31;

    for (int c = warp; c < C_; c += 8) {
        const float* row = x + ((size_t)b * C_ + c) * N_;
        float s = 0.f;
        for (int n = lane; n < N_; n += 32) s += row[n];
        #pragma unroll
        for (int off = 16; off > 0; off >>= 1)
            s += __shfl_xor_sync(0xffffffffu, s, off);
        if (lane == 0) y[c] = s / (float)N_;
    }
    __syncthreads();
    if (tid < 8) {
        float a = 0.f;
        for (int c = 0; c < C_; c++) a += w1[tid * C_ + c] * y[c];
        y1[tid] = fmaxf(a, 0.f);
    }
    __syncthreads();
    if (tid < C_) {
        float a = 0.f;
        #pragma unroll
        for (int r = 0; r < 8; r++) a += w2[tid * 8 + r] * y1[r];
        g_se[b * C_ + tid] = 1.f / (1.f + __expf(-a));
    }
}

// ---------------------------------------------------------------------------
// Flash attention: fp16 MMA, register-resident P and Q fragments,
// one __syncthreads per j-tile. grid (N/128, B), block 256.
// ---------------------------------------------------------------------------
__global__ void __launch_bounds__(256, 1) attn_kernel(
    const float* __restrict__ x,
    const float* __restrict__ gamma,
    float* __restrict__ out)
{
    extern __shared__ __half smh[];
    uint32_t sb = (uint32_t)__cvta_generic_to_shared(smh);

    const int tid  = threadIdx.x;
    const int b    = blockIdx.y;
    const int i0   = blockIdx.x * BM;
    const int warp = tid >> 5, lane = tid & 31;
    const int quad = lane >> 2, qt = lane & 3;

    const size_t bcn = (size_t)b * C_ * N_;
    const __half* qb = g_qh + (size_t)b * N_ * C_;
    const __half* kb = g_kh + (size_t)b * N_ * C_;
    const __half* vb = g_vh + (size_t)b * C_ * N_;

    // ---- prologue: stage Q [i][c], K0 [j][c], V0 [c][j] ----
    #pragma unroll
    for (int c2 = 0; c2 < 8; c2++) {
        int ch = tid + c2*256;
        int i = ch >> 4, cb = ch & 15;
        cpa16(sb + 2u*(OFF_Q + i*SQh + cb*8), qb + (size_t)(i0 + i)*C_ + cb*8);
    }
    #pragma unroll
    for (int c2 = 0; c2 < 4; c2++) {
        int ch = tid + c2*256;
        int j = ch >> 4, cb = ch & 15;
        cpa16(sb + 2u*(OFF_K + j*SKh + cb*8), kb + (size_t)j*C_ + cb*8);
    }
    #pragma unroll
    for (int c2 = 0; c2 < 4; c2++) {
        int ch = tid + c2*256;
        int c = ch >> 3, cb = ch & 7;
        cpa16(sb + 2u*(OFF_V + c*SVh + cb*8), vb + (size_t)c*N_ + cb*8);
    }
    cp_commit();
    cp_wait0();
    __syncthreads();

    const int r16  = lane & 15;
    const int ahi  = (lane >> 4) * 8;
    const int brow = (lane & 7) + ((lane >> 4) & 1) * 8;
    const int bcol = ((lane >> 3) & 1) * 8;

    // ---- Q fragments: loop-invariant, keep in registers ----
    uint32_t qa[8][4];
    {
        const uint32_t aQ = sb + 2u*(OFF_Q + (warp*16 + r16)*SQh + ahi);
        #pragma unroll
        for (int kc = 0; kc < 8; kc++)
            ldsm4(qa[kc][0], qa[kc][1], qa[kc][2], qa[kc][3], aQ + 32u*kc);
    }

    // ---- prefetch tile 1 ----
    #pragma unroll
    for (int c2 = 0; c2 < 4; c2++) {
        int ch = tid + c2*256;
        int j = ch >> 4, cb = ch & 15;
        cpa16(sb + 2u*(OFF_K + BN*SKh + j*SKh + cb*8), kb + (size_t)(BN + j)*C_ + cb*8);
    }
    #pragma unroll
    for (int c2 = 0; c2 < 4; c2++) {
        int ch = tid + c2*256;
        int c = ch >> 3, cb = ch & 7;
        cpa16(sb + 2u*(OFF_V + C_*SVh + c*SVh + cb*8), vb + (size_t)c*N_ + BN + cb*8);
    }
    cp_commit();

    float o[16][4];
    #pragma unroll
    for (int ct = 0; ct < 16; ct++)
        #pragma unroll
        for (int r = 0; r < 4; r++) o[ct][r] = 0.f;
    float m0 = -CUDART_INF_F, m1 = -CUDART_INF_F, l0 = 0.f, l1 = 0.f;

    for (int t = 0; t < 36; t++) {
        if (t > 0) {
            cp_wait0();
            __syncthreads();
            if (t < 35) {
                const int jn = (t + 1) * BN;
                const uint32_t kdst = sb + 2u*(OFF_K + ((t+1)&1)*BN*SKh);
                const uint32_t vdst = sb + 2u*(OFF_V + ((t+1)&1)*C_*SVh);
                #pragma unroll
                for (int c2 = 0; c2 < 4; c2++) {
                    int ch = tid + c2*256;
                    int j = ch >> 4, cb = ch & 15;
                    cpa16(kdst + 2u*(j*SKh + cb*8), kb + (size_t)(jn + j)*C_ + cb*8);
                }
                #pragma unroll
                for (int c2 = 0; c2 < 4; c2++) {
                    int ch = tid + c2*256;
                    int c = ch >> 3, cb = ch & 7;
                    cpa16(vdst + 2u*(c*SVh + cb*8), vb + (size_t)c*N_ + jn + cb*8);
                }
                cp_commit();
            }
        }

        // ---- S = Q K^T ----
        float s[8][4];
        #pragma unroll
        for (int nt = 0; nt < 8; nt++)
            #pragma unroll
            for (int r = 0; r < 4; r++) s[nt][r] = 0.f;

        const uint32_t kB = sb + 2u*(OFF_K + (t & 1)*BN*SKh + brow*SKh + bcol);
        #pragma unroll
        for (int kc = 0; kc < 8; kc++) {
            #pragma unroll
            for (int np = 0; np < 4; np++) {
                uint32_t b0,b1,b2,b3;
                ldsm4(b0,b1,b2,b3, kB + 2u*(np*16*SKh + kc*16));
                mma16(s[2*np],   qa[kc][0],qa[kc][1],qa[kc][2],qa[kc][3], b0,b1);
                mma16(s[2*np+1], qa[kc][0],qa[kc][1],qa[kc][2],qa[kc][3], b2,b3);
            }
        }

        // ---- online softmax; P packed directly into A-fragment registers ----
        float mt0 = -CUDART_INF_F, mt1 = -CUDART_INF_F;
        #pragma unroll
        for (int nt = 0; nt < 8; nt++) {
            mt0 = fmaxf(mt0, fmaxf(s[nt][0], s[nt][1]));
            mt1 = fmaxf(mt1, fmaxf(s[nt][2], s[nt][3]));
        }
        #pragma unroll
        for (int off = 1; off < 4; off <<= 1) {
            mt0 = fmaxf(mt0, __shfl_xor_sync(0xffffffffu, mt0, off));
            mt1 = fmaxf(mt1, __shfl_xor_sync(0xffffffffu, mt1, off));
        }
        float mn0 = fmaxf(m0, mt0), mn1 = fmaxf(m1, mt1);
        float cor0 = __expf(m0 - mn0), cor1 = __expf(m1 - mn1);
        float rs0 = 0.f, rs1 = 0.f;
        uint32_t pa0[8], pa1[8];
        #pragma unroll
        for (int nt = 0; nt < 8; nt++) {
            float p00 = __expf(s[nt][0] - mn0);
            float p01 = __expf(s[nt][1] - mn0);
            float p10 = __expf(s[nt][2] - mn1);
            float p11 = __expf(s[nt][3] - mn1);
            rs0 += p00 + p01; rs1 += p10 + p11;
            pa0[nt] = h2u(__floats2half2_rn(p00, p01));   // row g
            pa1[nt] = h2u(__floats2half2_rn(p10, p11));   // row g+8
        }
        #pragma unroll
        for (int off = 1; off < 4; off <<= 1) {
            rs0 += __shfl_xor_sync(0xffffffffu, rs0, off);
            rs1 += __shfl_xor_sync(0xffffffffu, rs1, off);
        }
        l0 = l0 * cor0 + rs0; m0 = mn0;
        l1 = l1 * cor1 + rs1; m1 = mn1;
        #pragma unroll
        for (int ct = 0; ct < 16; ct++) {
            o[ct][0] *= cor0; o[ct][1] *= cor0;
            o[ct][2] *= cor1; o[ct][3] *= cor1;
        }

        // ---- O += P V  (A from registers) ----
        const uint32_t vB = sb + 2u*(OFF_V + (t & 1)*C_*SVh + brow*SVh + bcol);
        #pragma unroll
        for (int kc = 0; kc < 4; kc++) {
            uint32_t a0 = pa0[2*kc], a1 = pa1[2*kc];
            uint32_t a2 = pa0[2*kc+1], a3 = pa1[2*kc+1];
            #pragma unroll
            for (int np = 0; np < 8; np++) {
                uint32_t b0,b1,b2,b3;
                ldsm4(b0,b1,b2,b3, vB + 2u*(np*16*SVh + kc*16));
                mma16(o[2*np],   a0,a1,a2,a3, b0,b1);
                mma16(o[2*np+1], a0,a1,a2,a3, b2,b3);
            }
        }
    }

    // ---- epilogue: out = gamma * O/l + x * se ----
    const float gam = gamma[0];
    const float inv0 = 1.f / l0, inv1 = 1.f / l1;
    const int ir0 = i0 + warp*16 + quad, ir1 = ir0 + 8;
    #pragma unroll
    for (int ct = 0; ct < 16; ct++) {
        int c0 = ct*8 + qt*2;
        float se0 = g_se[b*C_ + c0], se1 = g_se[b*C_ + c0 + 1];
        size_t base0 = bcn + (size_t)c0 * N_;
        size_t base1 = base0 + N_;
        out[base0 + ir0] = gam * o[ct][0] * inv0 + x[base0 + ir0] * se0;
        out[base1 + ir0] = gam * o[ct][1] * inv0 + x[base1 + ir0] * se1;
        out[base0 + ir1] = gam * o[ct][2] * inv1 + x[base0 + ir1] * se0;
        out[base1 + ir1] = gam * o[ct][3] * inv1 + x[base1 + ir1] * se1;
    }
}

// ---------------------------------------------------------------------------
extern "C" void kernel_launch(void* const* d_in, const int* in_sizes, int n_in,
                              void* d_out, int out_size)
{
    const float* x     = (const float*)d_in[0];
    const float* Wq    = (const float*)d_in[1];
    const float* bq    = (const float*)d_in[2];
    const float* Wk    = (const float*)d_in[3];
    const float* bk    = (const float*)d_in[4];
    const float* Wv    = (const float*)d_in[5];
    const float* bv    = (const float*)d_in[6];
    const float* se_w1 = (const float*)d_in[7];
    const float* se_w2 = (const float*)d_in[8];
    const float* gamma = (const float*)d_in[9];
    float* out = (float*)d_out;

    static int smem_set = 0;
    if (!smem_set) {
        cudaFuncSetAttribute(attn_kernel,
                             cudaFuncAttributeMaxDynamicSharedMemorySize,
                             SMEM_HALFS * (int)sizeof(__half));
        cudaFuncSetAttribute(qkv_mma_kernel,
                             cudaFuncAttributeMaxDynamicSharedMemorySize,
                             QKV_SMEM_HALFS * (int)sizeof(__half));
        smem_set = 1;
    }

    prep_kernel<<<(X2_TOTAL + W2_TOTAL + 255)/256, 256>>>(x, Wq, Wk, Wv);
    qkv_mma_kernel<<<dim3(N_/128, B_), 256, QKV_SMEM_HALFS * sizeof(__half)>>>(bq, bk, bv);
    se_kernel<<<B_, 256>>>(x, se_w1, se_w2);
    attn_kernel<<<dim3(N_/BM, B_), 256, SMEM_HALFS * sizeof(__half)>>>(x, gamma, out);
}

// round 6
// speedup vs baseline: 1.4364x; 1.4364x over previous
#include <cuda_runtime.h>
#include <cuda_fp16.h>
#include <math_constants.h>
#include <cstdint>

#define B_ 8
#define C_ 128
#define N_ 2304
#define BM 128
#define BN 64

// ---------------- attention smem strides (halfs) ----------------
#define SQh 136
#define SKh 136
#define SVh 72
#define SPh 72
#define OFF_Q 0
#define OFF_K (BM*SQh)                    // 17408
#define OFF_V (OFF_K + 2*BN*SKh)          // 34816
#define OFF_P (OFF_V + 2*C_*SVh)          // 53248
#define SMEM_HALFS (OFF_P + BM*SPh)       // 62464 halfs = 124928 B

// ---------------- qkv smem strides (halfs) ----------------
#define SX 136
#define SW 136
#define ST 136
#define QOFF_X  0
#define QOFF_W0 (C_*SX)
#define QOFF_W1 (QOFF_W0 + C_*SW)
#define QOFF_T  (QOFF_W1 + C_*SW)
#define QKV_SMEM_HALFS (QOFF_T + C_*ST)

__device__ __half g_qh[B_*N_*C_];   // [b][n][c]
__device__ __half g_kh[B_*N_*C_];   // [b][n][c]
__device__ __half g_vh[B_*C_*N_];   // [b][c][n]
__device__ __half g_wh[3*C_*C_];    // [which][o][c]
__device__ float  g_se[B_*C_];

// ---------------------------------------------------------------------------
__device__ __forceinline__ void cpa16(uint32_t s, const void* g){
    asm volatile("cp.async.cg.shared.global [%0], [%1], 16;" :: "r"(s), "l"(g));
}
__device__ __forceinline__ void cp_commit(){ asm volatile("cp.async.commit_group;"); }
__device__ __forceinline__ void cp_wait1(){ asm volatile("cp.async.wait_group 1;"); }
__device__ __forceinline__ void cp_wait0(){ asm volatile("cp.async.wait_group 0;"); }

__device__ __forceinline__ void ldsm4(uint32_t& r0,uint32_t& r1,uint32_t& r2,uint32_t& r3,
                                      uint32_t a){
    asm volatile("ldmatrix.sync.aligned.m8n8.x4.shared.b16 {%0,%1,%2,%3}, [%4];"
        : "=r"(r0),"=r"(r1),"=r"(r2),"=r"(r3) : "r"(a));
}
__device__ __forceinline__ void ldsm4t(uint32_t& r0,uint32_t& r1,uint32_t& r2,uint32_t& r3,
                                       uint32_t a){
    asm volatile("ldmatrix.sync.aligned.m8n8.x4.trans.shared.b16 {%0,%1,%2,%3}, [%4];"
        : "=r"(r0),"=r"(r1),"=r"(r2),"=r"(r3) : "r"(a));
}
__device__ __forceinline__ void sts32(uint32_t a, uint32_t v){
    asm volatile("st.shared.b32 [%0], %1;" :: "r"(a), "r"(v));
}
__device__ __forceinline__ void mma16(float* d, uint32_t a0,uint32_t a1,uint32_t a2,uint32_t a3,
                                      uint32_t b0,uint32_t b1){
    asm volatile(
      "mma.sync.aligned.m16n8k16.row.col.f32.f16.f16.f32 "
      "{%0,%1,%2,%3}, {%4,%5,%6,%7}, {%8,%9}, {%0,%1,%2,%3};"
      : "+f"(d[0]), "+f"(d[1]), "+f"(d[2]), "+f"(d[3])
      : "r"(a0), "r"(a1), "r"(a2), "r"(a3), "r"(b0), "r"(b1));
}
__device__ __forceinline__ uint32_t h2u(__half2 h){ return *reinterpret_cast<uint32_t*>(&h); }

// ---------------------------------------------------------------------------
// prep: fp32 -> fp16 for the 3 weight matrices only
// ---------------------------------------------------------------------------
#define W2_TOTAL (3*C_*C_/2)
__global__ __launch_bounds__(256) void prep_kernel(
    const float* __restrict__ Wq,
    const float* __restrict__ Wk,
    const float* __restrict__ Wv)
{
    int idx = blockIdx.x * 256 + threadIdx.x;
    if (idx < W2_TOTAL) {
        int which = idx / (C_*C_/2);
        int r = idx - which * (C_*C_/2);
        const float* Wm = (which == 0) ? Wq : (which == 1) ? Wk : Wv;
        float2 v = ((const float2*)Wm)[r];
        ((__half2*)g_wh)[idx] = __floats2half2_rn(v.x, v.y);
    }
}

// ---------------------------------------------------------------------------
// QKV via fp16 tensor cores; x converted fp32->fp16 inline while staging.
// grid (N/128, B), block 256 (8 warps).
// ---------------------------------------------------------------------------
__global__ void __launch_bounds__(256, 1) qkv_mma_kernel(
    const float* __restrict__ x,
    const float* __restrict__ bq,
    const float* __restrict__ bk,
    const float* __restrict__ bv)
{
    extern __shared__ __half smh[];
    uint32_t sb = (uint32_t)__cvta_generic_to_shared(smh);

    const int tid  = threadIdx.x;
    const int b    = blockIdx.y;
    const int n0   = blockIdx.x * 128;
    const int warp = tid >> 5, lane = tid & 31;
    const int quad = lane >> 2, qt = lane & 3;

    const float* xb = x + (size_t)b * C_ * N_;

    // W0 via cp.async
    #pragma unroll
    for (int c2 = 0; c2 < 8; c2++) {
        int ch = tid + c2*256;
        int o = ch >> 4, cb = ch & 15;
        cpa16(sb + 2u*(QOFF_W0 + o*SW + cb*8), g_wh + o*C_ + cb*8);
    }
    cp_commit();

    // x tile [c][n]: fp32 load + convert + smem store
    #pragma unroll
    for (int c2 = 0; c2 < 8; c2++) {
        int ch = tid + c2*256;
        int c = ch >> 4, nb = ch & 15;
        const float* src = xb + (size_t)c*N_ + n0 + nb*8;
        float4 v0 = *(const float4*)src;
        float4 v1 = *(const float4*)(src + 4);
        uint4 hv;
        hv.x = h2u(__floats2half2_rn(v0.x, v0.y));
        hv.y = h2u(__floats2half2_rn(v0.z, v0.w));
        hv.z = h2u(__floats2half2_rn(v1.x, v1.y));
        hv.w = h2u(__floats2half2_rn(v1.z, v1.w));
        *(uint4*)&smh[QOFF_X + c*SX + nb*8] = hv;
    }
    cp_wait0();
    __syncthreads();

    // prefetch W1
    #pragma unroll
    for (int c2 = 0; c2 < 8; c2++) {
        int ch = tid + c2*256;
        int o = ch >> 4, cb = ch & 15;
        cpa16(sb + 2u*(QOFF_W1 + o*SW + cb*8), g_wh + C_*C_ + o*C_ + cb*8);
    }
    cp_commit();

    const int r16 = lane & 15;
    const int hi8 = (lane >> 4) * 8;
    const uint32_t bX = sb + 2u*(QOFF_X + r16*SX + hi8);
    const uint32_t tst0 = sb + 2u*(QOFF_T + (warp*16 + quad)*ST + qt*2);
    const uint32_t tst1 = tst0 + 2u*8*ST;

    const int o_r0 = warp*16 + quad, o_r1 = o_r0 + 8;

    #pragma unroll
    for (int which = 0; which < 3; which++) {
        const uint32_t wbuf = sb + 2u*((which & 1) ? QOFF_W1 : QOFF_W0);
        const uint32_t aW = wbuf + 2u*((warp*16 + r16)*SW + hi8);

        float acc[16][4];
        #pragma unroll
        for (int nt = 0; nt < 16; nt++)
            #pragma unroll
            for (int r = 0; r < 4; r++) acc[nt][r] = 0.f;

        #pragma unroll
        for (int kc = 0; kc < 8; kc++) {
            uint32_t a0,a1,a2,a3;
            ldsm4(a0,a1,a2,a3, aW + 32u*kc);
            #pragma unroll
            for (int nt16 = 0; nt16 < 8; nt16++) {
                uint32_t b0,b1,b2,b3;
                ldsm4t(b0,b1,b2,b3, bX + 2u*(kc*16*SX + nt16*16));
                mma16(acc[2*nt16],   a0,a1,a2,a3, b0,b1);
                mma16(acc[2*nt16+1], a0,a1,a2,a3, b2,b3);
            }
        }

        const float* bias = (which == 0) ? bq : (which == 1) ? bk : bv;
        float b0f = bias[o_r0], b1f = bias[o_r1];
        #pragma unroll
        for (int nt = 0; nt < 16; nt++) {
            sts32(tst0 + 16u*nt, h2u(__floats2half2_rn(acc[nt][0] + b0f, acc[nt][1] + b0f)));
            sts32(tst1 + 16u*nt, h2u(__floats2half2_rn(acc[nt][2] + b1f, acc[nt][3] + b1f)));
        }
        __syncthreads();

        if (which == 0) {
            #pragma unroll
            for (int c2 = 0; c2 < 8; c2++) {
                int ch = tid + c2*256;
                int o = ch >> 4, cb = ch & 15;
                cpa16(sb + 2u*(QOFF_W0 + o*SW + cb*8), g_wh + 2*C_*C_ + o*C_ + cb*8);
            }
            cp_commit();
        }

        if (which < 2) {
            __half* dsth = (which == 0) ? g_qh : g_kh;
            #pragma unroll
            for (int c2 = 0; c2 < 8; c2++) {
                int ch = tid + c2*256;
                int n = ch >> 4, ob = ch & 15;
                __half tmp[8];
                #pragma unroll
                for (int u = 0; u < 8; u++) tmp[u] = smh[QOFF_T + (ob*8 + u)*ST + n];
                *(uint4*)(dsth + ((size_t)b*N_ + n0 + n)*C_ + ob*8) = *(uint4*)tmp;
            }
        } else {
            #pragma unroll
            for (int c2 = 0; c2 < 8; c2++) {
                int ch = tid + c2*256;
                int o = ch >> 4, nb = ch & 15;
                uint4 v = *(uint4*)&smh[QOFF_T + o*ST + nb*8];
                *(uint4*)(g_vh + ((size_t)b*C_ + o)*N_ + n0 + nb*8) = v;
            }
        }

        if (which < 2) { cp_wait0(); }
        __syncthreads();
    }
}

// ---------------------------------------------------------------------------
// SE branch
// ---------------------------------------------------------------------------
__global__ __launch_bounds__(256) void se_kernel(
    const float* __restrict__ x,
    const float* __restrict__ w1,
    const float* __restrict__ w2)
{
    __shared__ float y[C_];
    __shared__ float y1[C_/16];
    int b = blockIdx.x;
    int tid = threadIdx.x;
    int warp = tid >> 5, lane = tid & 31;

    for (int c = warp; c < C_; c += 8) {
        const float* row = x + ((size_t)b * C_ + c) * N_;
        float s = 0.f;
        for (int n = lane; n < N_; n += 32) s += row[n];
        #pragma unroll
        for (int off = 16; off > 0; off >>= 1)
            s += __shfl_xor_sync(0xffffffffu, s, off);
        if (lane == 0) y[c] = s / (float)N_;
    }
    __syncthreads();
    if (tid < 8) {
        float a = 0.f;
        for (int c = 0; c < C_; c++) a += w1[tid * C_ + c] * y[c];
        y1[tid] = fmaxf(a, 0.f);
    }
    __syncthreads();
    if (tid < C_) {
        float a = 0.f;
        #pragma unroll
        for (int r = 0; r < 8; r++) a += w2[tid * 8 + r] * y1[r];
        g_se[b * C_ + tid] = 1.f / (1.f + __expf(-a));
    }
}

// ---------------------------------------------------------------------------
// Flash attention: fp16 MMA, R4 compute body (P via smem, Q ldsm per tile),
// single __syncthreads per j-tile with K and V double-buffered.
// grid (N/128, B), block 256 (8 warps).
// ---------------------------------------------------------------------------
__global__ void __launch_bounds__(256, 1) attn_kernel(
    const float* __restrict__ x,
    const float* __restrict__ gamma,
    float* __restrict__ out)
{
    extern __shared__ __half smh[];
    uint32_t sb = (uint32_t)__cvta_generic_to_shared(smh);

    const int tid  = threadIdx.x;
    const int b    = blockIdx.y;
    const int i0   = blockIdx.x * BM;
    const int warp = tid >> 5, lane = tid & 31;
    const int quad = lane >> 2, qt = lane & 3;

    const size_t bcn = (size_t)b * C_ * N_;
    const __half* qb = g_qh + (size_t)b * N_ * C_;
    const __half* kb = g_kh + (size_t)b * N_ * C_;
    const __half* vb = g_vh + (size_t)b * C_ * N_;

    // ---- prologue: group A = (Q, K0, V0); group B = (K1, V1) ----
    #pragma unroll
    for (int c2 = 0; c2 < 8; c2++) {
        int ch = tid + c2*256;
        int i = ch >> 4, cb = ch & 15;
        cpa16(sb + 2u*(OFF_Q + i*SQh + cb*8), qb + (size_t)(i0 + i)*C_ + cb*8);
    }
    #pragma unroll
    for (int c2 = 0; c2 < 4; c2++) {
        int ch = tid + c2*256;
        int j = ch >> 4, cb = ch & 15;
        cpa16(sb + 2u*(OFF_K + j*SKh + cb*8), kb + (size_t)j*C_ + cb*8);
    }
    #pragma unroll
    for (int c2 = 0; c2 < 4; c2++) {
        int ch = tid + c2*256;
        int c = ch >> 3, cb = ch & 7;
        cpa16(sb + 2u*(OFF_V + c*SVh + cb*8), vb + (size_t)c*N_ + cb*8);
    }
    cp_commit();
    #pragma unroll
    for (int c2 = 0; c2 < 4; c2++) {
        int ch = tid + c2*256;
        int j = ch >> 4, cb = ch & 15;
        cpa16(sb + 2u*(OFF_K + BN*SKh + j*SKh + cb*8), kb + (size_t)(BN + j)*C_ + cb*8);
    }
    #pragma unroll
    for (int c2 = 0; c2 < 4; c2++) {
        int ch = tid + c2*256;
        int c = ch >> 3, cb = ch & 7;
        cpa16(sb + 2u*(OFF_V + C_*SVh + c*SVh + cb*8), vb + (size_t)c*N_ + BN + cb*8);
    }
    cp_commit();
    cp_wait1();            // group A resident
    __syncthreads();

    float o[16][4];
    #pragma unroll
    for (int ct = 0; ct < 16; ct++)
        #pragma unroll
        for (int r = 0; r < 4; r++) o[ct][r] = 0.f;
    float m0 = -CUDART_INF_F, m1 = -CUDART_INF_F, l0 = 0.f, l1 = 0.f;

    const int r16  = lane & 15;
    const int ahi  = (lane >> 4) * 8;
    const int brow = (lane & 7) + ((lane >> 4) & 1) * 8;
    const int bcol = ((lane >> 3) & 1) * 8;

    const uint32_t aQ   = sb + 2u*(OFF_Q + (warp*16 + r16)*SQh + ahi);
    const uint32_t aP   = sb + 2u*(OFF_P + (warp*16 + r16)*SPh + ahi);
    const uint32_t pst0 = sb + 2u*(OFF_P + (warp*16 + quad)*SPh + qt*2);
    const uint32_t pst1 = pst0 + 2u*8*SPh;

    for (int t = 0; t < 36; t++) {
        if (t > 0) {
            cp_wait0();        // tile t (K_t, V_t) resident
            __syncthreads();   // all warps done reading buffers (t-1)&1 == (t+1)&1
            if (t < 35) {
                const int jn = (t + 1) * BN;
                const uint32_t kdst = sb + 2u*(OFF_K + ((t+1)&1)*BN*SKh);
                const uint32_t vdst = sb + 2u*(OFF_V + ((t+1)&1)*C_*SVh);
                #pragma unroll
                for (int c2 = 0; c2 < 4; c2++) {
                    int ch = tid + c2*256;
                    int j = ch >> 4, cb = ch & 15;
                    cpa16(kdst + 2u*(j*SKh + cb*8), kb + (size_t)(jn + j)*C_ + cb*8);
                }
                #pragma unroll
                for (int c2 = 0; c2 < 4; c2++) {
                    int ch = tid + c2*256;
                    int c = ch >> 3, cb = ch & 7;
                    cpa16(vdst + 2u*(c*SVh + cb*8), vb + (size_t)c*N_ + jn + cb*8);
                }
                cp_commit();
            }
        }

        // ---- S = Q K^T ----
        float s[8][4];
        #pragma unroll
        for (int nt = 0; nt < 8; nt++)
            #pragma unroll
            for (int r = 0; r < 4; r++) s[nt][r] = 0.f;

        const uint32_t kB = sb + 2u*(OFF_K + (t & 1)*BN*SKh + brow*SKh + bcol);
        #pragma unroll
        for (int kc = 0; kc < 8; kc++) {
            uint32_t a0,a1,a2,a3;
            ldsm4(a0,a1,a2,a3, aQ + 32u*kc);
            #pragma unroll
            for (int np = 0; np < 4; np++) {
                uint32_t b0,b1,b2,b3;
                ldsm4(b0,b1,b2,b3, kB + 2u*(np*16*SKh + kc*16));
                mma16(s[2*np],   a0,a1,a2,a3, b0,b1);
                mma16(s[2*np+1], a0,a1,a2,a3, b2,b3);
            }
        }

        // ---- online softmax; rows r0 = warp*16+quad, r1 = r0+8 ----
        float mt0 = -CUDART_INF_F, mt1 = -CUDART_INF_F;
        #pragma unroll
        for (int nt = 0; nt < 8; nt++) {
            mt0 = fmaxf(mt0, fmaxf(s[nt][0], s[nt][1]));
            mt1 = fmaxf(mt1, fmaxf(s[nt][2], s[nt][3]));
        }
        #pragma unroll
        for (int off = 1; off < 4; off <<= 1) {
            mt0 = fmaxf(mt0, __shfl_xor_sync(0xffffffffu, mt0, off));
            mt1 = fmaxf(mt1, __shfl_xor_sync(0xffffffffu, mt1, off));
        }
        float mn0 = fmaxf(m0, mt0), mn1 = fmaxf(m1, mt1);
        float cor0 = __expf(m0 - mn0), cor1 = __expf(m1 - mn1);
        float rs0 = 0.f, rs1 = 0.f;
        #pragma unroll
        for (int nt = 0; nt < 8; nt++) {
            float p00 = __expf(s[nt][0] - mn0);
            float p01 = __expf(s[nt][1] - mn0);
            float p10 = __expf(s[nt][2] - mn1);
            float p11 = __expf(s[nt][3] - mn1);
            rs0 += p00 + p01; rs1 += p10 + p11;
            sts32(pst0 + 16u*nt, h2u(__floats2half2_rn(p00, p01)));
            sts32(pst1 + 16u*nt, h2u(__floats2half2_rn(p10, p11)));
        }
        #pragma unroll
        for (int off = 1; off < 4; off <<= 1) {
            rs0 += __shfl_xor_sync(0xffffffffu, rs0, off);
            rs1 += __shfl_xor_sync(0xffffffffu, rs1, off);
        }
        l0 = l0 * cor0 + rs0; m0 = mn0;
        l1 = l1 * cor1 + rs1; m1 = mn1;
        #pragma unroll
        for (int ct = 0; ct < 16; ct++) {
            o[ct][0] *= cor0; o[ct][1] *= cor0;
            o[ct][2] *= cor1; o[ct][3] *= cor1;
        }
        __syncwarp();          // P rows warp-private: order st -> ldmatrix

        // ---- O += P V ----
        const uint32_t vB = sb + 2u*(OFF_V + (t & 1)*C_*SVh + brow*SVh + bcol);
        #pragma unroll
        for (int kc = 0; kc < 4; kc++) {
            uint32_t a0,a1,a2,a3;
            ldsm4(a0,a1,a2,a3, aP + 32u*kc);
            #pragma unroll
            for (int np = 0; np < 8; np++) {
                uint32_t b0,b1,b2,b3;
                ldsm4(b0,b1,b2,b3, vB + 2u*(np*16*SVh + kc*16));
                mma16(o[2*np],   a0,a1,a2,a3, b0,b1);
                mma16(o[2*np+1], a0,a1,a2,a3, b2,b3);
            }
        }
    }

    // ---- epilogue: out = gamma * O/l + x * se ----
    const float gam = gamma[0];
    const float inv0 = 1.f / l0, inv1 = 1.f / l1;
    const int ir0 = i0 + warp*16 + quad, ir1 = ir0 + 8;
    #pragma unroll
    for (int ct = 0; ct < 16; ct++) {
        int c0 = ct*8 + qt*2;
        float se0 = g_se[b*C_ + c0], se1 = g_se[b*C_ + c0 + 1];
        size_t base0 = bcn + (size_t)c0 * N_;
        size_t base1 = base0 + N_;
        out[base0 + ir0] = gam * o[ct][0] * inv0 + x[base0 + ir0] * se0;
        out[base1 + ir0] = gam * o[ct][1] * inv0 + x[base1 + ir0] * se1;
        out[base0 + ir1] = gam * o[ct][2] * inv1 + x[base0 + ir1] * se0;
        out[base1 + ir1] = gam * o[ct][3] * inv1 + x[base1 + ir1] * se1;
    }
}

// ---------------------------------------------------------------------------
extern "C" void kernel_launch(void* const* d_in, const int* in_sizes, int n_in,
                              void* d_out, int out_size)
{
    const float* x     = (const float*)d_in[0];
    const float* Wq    = (const float*)d_in[1];
    const float* bq    = (const float*)d_in[2];
    const float* Wk    = (const float*)d_in[3];
    const float* bk    = (const float*)d_in[4];
    const float* Wv    = (const float*)d_in[5];
    const float* bv    = (const float*)d_in[6];
    const float* se_w1 = (const float*)d_in[7];
    const float* se_w2 = (const float*)d_in[8];
    const float* gamma = (const float*)d_in[9];
    float* out = (float*)d_out;

    static int smem_set = 0;
    if (!smem_set) {
        cudaFuncSetAttribute(attn_kernel,
                             cudaFuncAttributeMaxDynamicSharedMemorySize,
                             SMEM_HALFS * (int)sizeof(__half));
        cudaFuncSetAttribute(qkv_mma_kernel,
                             cudaFuncAttributeMaxDynamicSharedMemorySize,
                             QKV_SMEM_HALFS * (int)sizeof(__half));
        smem_set = 1;
    }

    prep_kernel<<<(W2_TOTAL + 255)/256, 256>>>(Wq, Wk, Wv);
    qkv_mma_kernel<<<dim3(N_/128, B_), 256, QKV_SMEM_HALFS * sizeof(__half)>>>(x, bq, bk, bv);
    se_kernel<<<B_, 256>>>(x, se_w1, se_w2);
    attn_kernel<<<dim3(N_/BM, B_), 256, SMEM_HALFS * sizeof(__half)>>>(x, gamma, out);
}

// round 7
// speedup vs baseline: 1.6301x; 1.1349x over previous
#include <cuda_runtime.h>
#include <cuda_fp16.h>
#include <math_constants.h>
#include <cstdint>

#define B_ 8
#define C_ 128
#define N_ 2304
#define BM 64
#define BN 64

// ---------------- attention smem strides (halfs) ----------------
#define SQh 136
#define SKh 136
#define SVh 72
#define SPh 72
#define OFF_Q 0                           // 64*136   = 8704
#define OFF_K (BM*SQh)                    // + 2*64*136 = 17408
#define OFF_V (OFF_K + 2*BN*SKh)          // + 2*128*72 = 18432
#define OFF_P (OFF_V + 2*C_*SVh)          // + 64*72    = 4608
#define SMEM_HALFS (OFF_P + BM*SPh)       // 49152 halfs = 98304 B

// ---------------- qkv smem strides (halfs) ----------------
#define SX 136
#define SW 136
#define ST 136
#define QOFF_X  0
#define QOFF_W0 (C_*SX)
#define QOFF_W1 (QOFF_W0 + C_*SW)
#define QOFF_T  (QOFF_W1 + C_*SW)
#define QKV_SMEM_HALFS (QOFF_T + C_*ST)

__device__ __half g_qh[B_*N_*C_];   // [b][n][c]
__device__ __half g_kh[B_*N_*C_];   // [b][n][c]
__device__ __half g_vh[B_*C_*N_];   // [b][c][n]
__device__ __half g_wh[3*C_*C_];    // [which][o][c]
__device__ float  g_ymean[B_*C_];
__device__ float  g_se[B_*C_];

// ---------------------------------------------------------------------------
__device__ __forceinline__ void cpa16(uint32_t s, const void* g){
    asm volatile("cp.async.cg.shared.global [%0], [%1], 16;" :: "r"(s), "l"(g));
}
__device__ __forceinline__ void cp_commit(){ asm volatile("cp.async.commit_group;"); }
__device__ __forceinline__ void cp_wait1(){ asm volatile("cp.async.wait_group 1;"); }
__device__ __forceinline__ void cp_wait0(){ asm volatile("cp.async.wait_group 0;"); }

__device__ __forceinline__ void ldsm4(uint32_t& r0,uint32_t& r1,uint32_t& r2,uint32_t& r3,
                                      uint32_t a){
    asm volatile("ldmatrix.sync.aligned.m8n8.x4.shared.b16 {%0,%1,%2,%3}, [%4];"
        : "=r"(r0),"=r"(r1),"=r"(r2),"=r"(r3) : "r"(a));
}
__device__ __forceinline__ void ldsm4t(uint32_t& r0,uint32_t& r1,uint32_t& r2,uint32_t& r3,
                                       uint32_t a){
    asm volatile("ldmatrix.sync.aligned.m8n8.x4.trans.shared.b16 {%0,%1,%2,%3}, [%4];"
        : "=r"(r0),"=r"(r1),"=r"(r2),"=r"(r3) : "r"(a));
}
__device__ __forceinline__ void sts32(uint32_t a, uint32_t v){
    asm volatile("st.shared.b32 [%0], %1;" :: "r"(a), "r"(v));
}
__device__ __forceinline__ void mma16(float* d, uint32_t a0,uint32_t a1,uint32_t a2,uint32_t a3,
                                      uint32_t b0,uint32_t b1){
    asm volatile(
      "mma.sync.aligned.m16n8k16.row.col.f32.f16.f16.f32 "
      "{%0,%1,%2,%3}, {%4,%5,%6,%7}, {%8,%9}, {%0,%1,%2,%3};"
      : "+f"(d[0]), "+f"(d[1]), "+f"(d[2]), "+f"(d[3])
      : "r"(a0), "r"(a1), "r"(a2), "r"(a3), "r"(b0), "r"(b1));
}
__device__ __forceinline__ uint32_t h2u(__half2 h){ return *reinterpret_cast<uint32_t*>(&h); }

// ---------------------------------------------------------------------------
// prep: fp32 -> fp16 for the 3 weight matrices
// ---------------------------------------------------------------------------
#define W2_TOTAL (3*C_*C_/2)
__global__ __launch_bounds__(256) void prep_kernel(
    const float* __restrict__ Wq,
    const float* __restrict__ Wk,
    const float* __restrict__ Wv)
{
    int idx = blockIdx.x * 256 + threadIdx.x;
    if (idx < W2_TOTAL) {
        int which = idx / (C_*C_/2);
        int r = idx - which * (C_*C_/2);
        const float* Wm = (which == 0) ? Wq : (which == 1) ? Wk : Wv;
        float2 v = ((const float2*)Wm)[r];
        ((__half2*)g_wh)[idx] = __floats2half2_rn(v.x, v.y);
    }
}

// ---------------------------------------------------------------------------
// QKV via fp16 tensor cores; x converted fp32->fp16 inline while staging.
// grid (N/128, B), block 256 (8 warps).
// ---------------------------------------------------------------------------
__global__ void __launch_bounds__(256, 1) qkv_mma_kernel(
    const float* __restrict__ x,
    const float* __restrict__ bq,
    const float* __restrict__ bk,
    const float* __restrict__ bv)
{
    extern __shared__ __half smh[];
    uint32_t sb = (uint32_t)__cvta_generic_to_shared(smh);

    const int tid  = threadIdx.x;
    const int b    = blockIdx.y;
    const int n0   = blockIdx.x * 128;
    const int warp = tid >> 5, lane = tid & 31;
    const int quad = lane >> 2, qt = lane & 3;

    const float* xb = x + (size_t)b * C_ * N_;

    #pragma unroll
    for (int c2 = 0; c2 < 8; c2++) {
        int ch = tid + c2*256;
        int o = ch >> 4, cb = ch & 15;
        cpa16(sb + 2u*(QOFF_W0 + o*SW + cb*8), g_wh + o*C_ + cb*8);
    }
    cp_commit();

    #pragma unroll
    for (int c2 = 0; c2 < 8; c2++) {
        int ch = tid + c2*256;
        int c = ch >> 4, nb = ch & 15;
        const float* src = xb + (size_t)c*N_ + n0 + nb*8;
        float4 v0 = *(const float4*)src;
        float4 v1 = *(const float4*)(src + 4);
        uint4 hv;
        hv.x = h2u(__floats2half2_rn(v0.x, v0.y));
        hv.y = h2u(__floats2half2_rn(v0.z, v0.w));
        hv.z = h2u(__floats2half2_rn(v1.x, v1.y));
        hv.w = h2u(__floats2half2_rn(v1.z, v1.w));
        *(uint4*)&smh[QOFF_X + c*SX + nb*8] = hv;
    }
    cp_wait0();
    __syncthreads();

    #pragma unroll
    for (int c2 = 0; c2 < 8; c2++) {
        int ch = tid + c2*256;
        int o = ch >> 4, cb = ch & 15;
        cpa16(sb + 2u*(QOFF_W1 + o*SW + cb*8), g_wh + C_*C_ + o*C_ + cb*8);
    }
    cp_commit();

    const int r16 = lane & 15;
    const int hi8 = (lane >> 4) * 8;
    const uint32_t bX = sb + 2u*(QOFF_X + r16*SX + hi8);
    const uint32_t tst0 = sb + 2u*(QOFF_T + (warp*16 + quad)*ST + qt*2);
    const uint32_t tst1 = tst0 + 2u*8*ST;

    const int o_r0 = warp*16 + quad, o_r1 = o_r0 + 8;

    #pragma unroll
    for (int which = 0; which < 3; which++) {
        const uint32_t wbuf = sb + 2u*((which & 1) ? QOFF_W1 : QOFF_W0);
        const uint32_t aW = wbuf + 2u*((warp*16 + r16)*SW + hi8);

        float acc[16][4];
        #pragma unroll
        for (int nt = 0; nt < 16; nt++)
            #pragma unroll
            for (int r = 0; r < 4; r++) acc[nt][r] = 0.f;

        #pragma unroll
        for (int kc = 0; kc < 8; kc++) {
            uint32_t a0,a1,a2,a3;
            ldsm4(a0,a1,a2,a3, aW + 32u*kc);
            #pragma unroll
            for (int nt16 = 0; nt16 < 8; nt16++) {
                uint32_t b0,b1,b2,b3;
                ldsm4t(b0,b1,b2,b3, bX + 2u*(kc*16*SX + nt16*16));
                mma16(acc[2*nt16],   a0,a1,a2,a3, b0,b1);
                mma16(acc[2*nt16+1], a0,a1,a2,a3, b2,b3);
            }
        }

        const float* bias = (which == 0) ? bq : (which == 1) ? bk : bv;
        float b0f = bias[o_r0], b1f = bias[o_r1];
        #pragma unroll
        for (int nt = 0; nt < 16; nt++) {
            sts32(tst0 + 16u*nt, h2u(__floats2half2_rn(acc[nt][0] + b0f, acc[nt][1] + b0f)));
            sts32(tst1 + 16u*nt, h2u(__floats2half2_rn(acc[nt][2] + b1f, acc[nt][3] + b1f)));
        }
        __syncthreads();

        if (which == 0) {
            #pragma unroll
            for (int c2 = 0; c2 < 8; c2++) {
                int ch = tid + c2*256;
                int o = ch >> 4, cb = ch & 15;
                cpa16(sb + 2u*(QOFF_W0 + o*SW + cb*8), g_wh + 2*C_*C_ + o*C_ + cb*8);
            }
            cp_commit();
        }

        if (which < 2) {
            __half* dsth = (which == 0) ? g_qh : g_kh;
            #pragma unroll
            for (int c2 = 0; c2 < 8; c2++) {
                int ch = tid + c2*256;
                int n = ch >> 4, ob = ch & 15;
                __half tmp[8];
                #pragma unroll
                for (int u = 0; u < 8; u++) tmp[u] = smh[QOFF_T + (ob*8 + u)*ST + n];
                *(uint4*)(dsth + ((size_t)b*N_ + n0 + n)*C_ + ob*8) = *(uint4*)tmp;
            }
        } else {
            #pragma unroll
            for (int c2 = 0; c2 < 8; c2++) {
                int ch = tid + c2*256;
                int o = ch >> 4, nb = ch & 15;
                uint4 v = *(uint4*)&smh[QOFF_T + o*ST + nb*8];
                *(uint4*)(g_vh + ((size_t)b*C_ + o)*N_ + n0 + nb*8) = v;
            }
        }

        if (which < 2) { cp_wait0(); }
        __syncthreads();
    }
}

// ---------------------------------------------------------------------------
// SE branch: parallel mean reduction (one CTA per (b,c) row), then tiny MLP.
// ---------------------------------------------------------------------------
__global__ __launch_bounds__(256) void se_reduce_kernel(const float* __restrict__ x)
{
    int bc = blockIdx.x;
    const float* row = x + (size_t)bc * N_;
    int tid = threadIdx.x;
    float s = 0.f;
    for (int n = tid; n < N_; n += 256) s += row[n];
    __shared__ float red[8];
    #pragma unroll
    for (int off = 16; off > 0; off >>= 1)
        s += __shfl_xor_sync(0xffffffffu, s, off);
    if ((tid & 31) == 0) red[tid >> 5] = s;
    __syncthreads();
    if (tid < 8) {
        float v = red[tid];
        #pragma unroll
        for (int off = 4; off > 0; off >>= 1)
            v += __shfl_xor_sync(0xffu, v, off);
        if (tid == 0) g_ymean[bc] = v / (float)N_;
    }
}

__global__ __launch_bounds__(256) void se_mlp_kernel(
    const float* __restrict__ w1,   // (8, 128)
    const float* __restrict__ w2)   // (128, 8)
{
    __shared__ float ysh[B_*C_];
    int tid = threadIdx.x;
    #pragma unroll
    for (int u = 0; u < 4; u++) ysh[tid + u*256] = g_ymean[tid + u*256];
    __syncthreads();

    int b = tid >> 5, lane = tid & 31;
    // hidden: lane computes partial for h = lane&7 over c-quarter (lane>>3)*32
    int h = lane & 7, cq = lane >> 3;
    float p = 0.f;
    #pragma unroll
    for (int u = 0; u < 32; u++) {
        int c = cq*32 + u;
        p += w1[h*C_ + c] * ysh[b*C_ + c];
    }
    p += __shfl_xor_sync(0xffffffffu, p, 8);
    p += __shfl_xor_sync(0xffffffffu, p, 16);
    float hv = fmaxf(p, 0.f);   // valid on lanes 0..7 (replicated on all cq groups)
    // broadcast y1[r] from lane r
    float y1[8];
    #pragma unroll
    for (int r = 0; r < 8; r++) y1[r] = __shfl_sync(0xffffffffu, hv, r);
    // outputs: 4 channels per lane
    #pragma unroll
    for (int u = 0; u < 4; u++) {
        int c = lane + u*32;
        float a = 0.f;
        #pragma unroll
        for (int r = 0; r < 8; r++) a += w2[c*8 + r] * y1[r];
        g_se[b*C_ + c] = 1.f / (1.f + __expf(-a));
    }
}

// ---------------------------------------------------------------------------
// Flash attention: BM=64, 4 warps (128 threads), 2 CTAs/SM.
// fp16 MMA, P via smem, K+V double-buffered, one __syncthreads per j-tile.
// grid (N/64, B), block 128.
// ---------------------------------------------------------------------------
__global__ void __launch_bounds__(128, 2) attn_kernel(
    const float* __restrict__ x,
    const float* __restrict__ gamma,
    float* __restrict__ out)
{
    extern __shared__ __half smh[];
    uint32_t sb = (uint32_t)__cvta_generic_to_shared(smh);

    const int tid  = threadIdx.x;
    const int b    = blockIdx.y;
    const int i0   = blockIdx.x * BM;
    const int warp = tid >> 5, lane = tid & 31;
    const int quad = lane >> 2, qt = lane & 3;

    const size_t bcn = (size_t)b * C_ * N_;
    const __half* qb = g_qh + (size_t)b * N_ * C_;
    const __half* kb = g_kh + (size_t)b * N_ * C_;
    const __half* vb = g_vh + (size_t)b * C_ * N_;

    // ---- prologue: group A = (Q, K0, V0); group B = (K1, V1) ----
    #pragma unroll
    for (int c2 = 0; c2 < 8; c2++) {
        int ch = tid + c2*128;
        int i = ch >> 4, cb = ch & 15;
        cpa16(sb + 2u*(OFF_Q + i*SQh + cb*8), qb + (size_t)(i0 + i)*C_ + cb*8);
    }
    #pragma unroll
    for (int c2 = 0; c2 < 8; c2++) {
        int ch = tid + c2*128;
        int j = ch >> 4, cb = ch & 15;
        cpa16(sb + 2u*(OFF_K + j*SKh + cb*8), kb + (size_t)j*C_ + cb*8);
    }
    #pragma unroll
    for (int c2 = 0; c2 < 8; c2++) {
        int ch = tid + c2*128;
        int c = ch >> 3, cb = ch & 7;
        cpa16(sb + 2u*(OFF_V + c*SVh + cb*8), vb + (size_t)c*N_ + cb*8);
    }
    cp_commit();
    #pragma unroll
    for (int c2 = 0; c2 < 8; c2++) {
        int ch = tid + c2*128;
        int j = ch >> 4, cb = ch & 15;
        cpa16(sb + 2u*(OFF_K + BN*SKh + j*SKh + cb*8), kb + (size_t)(BN + j)*C_ + cb*8);
    }
    #pragma unroll
    for (int c2 = 0; c2 < 8; c2++) {
        int ch = tid + c2*128;
        int c = ch >> 3, cb = ch & 7;
        cpa16(sb + 2u*(OFF_V + C_*SVh + c*SVh + cb*8), vb + (size_t)c*N_ + BN + cb*8);
    }
    cp_commit();
    cp_wait1();
    __syncthreads();

    float o[16][4];
    #pragma unroll
    for (int ct = 0; ct < 16; ct++)
        #pragma unroll
        for (int r = 0; r < 4; r++) o[ct][r] = 0.f;
    float m0 = -CUDART_INF_F, m1 = -CUDART_INF_F, l0 = 0.f, l1 = 0.f;

    const int r16  = lane & 15;
    const int ahi  = (lane >> 4) * 8;
    const int brow = (lane & 7) + ((lane >> 4) & 1) * 8;
    const int bcol = ((lane >> 3) & 1) * 8;

    const uint32_t aQ   = sb + 2u*(OFF_Q + (warp*16 + r16)*SQh + ahi);
    const uint32_t aP   = sb + 2u*(OFF_P + (warp*16 + r16)*SPh + ahi);
    const uint32_t pst0 = sb + 2u*(OFF_P + (warp*16 + quad)*SPh + qt*2);
    const uint32_t pst1 = pst0 + 2u*8*SPh;

    for (int t = 0; t < 36; t++) {
        if (t > 0) {
            cp_wait0();
            __syncthreads();
            if (t < 35) {
                const int jn = (t + 1) * BN;
                const uint32_t kdst = sb + 2u*(OFF_K + ((t+1)&1)*BN*SKh);
                const uint32_t vdst = sb + 2u*(OFF_V + ((t+1)&1)*C_*SVh);
                #pragma unroll
                for (int c2 = 0; c2 < 8; c2++) {
                    int ch = tid + c2*128;
                    int j = ch >> 4, cb = ch & 15;
                    cpa16(kdst + 2u*(j*SKh + cb*8), kb + (size_t)(jn + j)*C_ + cb*8);
                }
                #pragma unroll
                for (int c2 = 0; c2 < 8; c2++) {
                    int ch = tid + c2*128;
                    int c = ch >> 3, cb = ch & 7;
                    cpa16(vdst + 2u*(c*SVh + cb*8), vb + (size_t)c*N_ + jn + cb*8);
                }
                cp_commit();
            }
        }

        // ---- S = Q K^T ----
        float s[8][4];
        #pragma unroll
        for (int nt = 0; nt < 8; nt++)
            #pragma unroll
            for (int r = 0; r < 4; r++) s[nt][r] = 0.f;

        const uint32_t kB = sb + 2u*(OFF_K + (t & 1)*BN*SKh + brow*SKh + bcol);
        #pragma unroll
        for (int kc = 0; kc < 8; kc++) {
            uint32_t a0,a1,a2,a3;
            ldsm4(a0,a1,a2,a3, aQ + 32u*kc);
            #pragma unroll
            for (int np = 0; np < 4; np++) {
                uint32_t b0,b1,b2,b3;
                ldsm4(b0,b1,b2,b3, kB + 2u*(np*16*SKh + kc*16));
                mma16(s[2*np],   a0,a1,a2,a3, b0,b1);
                mma16(s[2*np+1], a0,a1,a2,a3, b2,b3);
            }
        }

        // ---- online softmax ----
        float mt0 = -CUDART_INF_F, mt1 = -CUDART_INF_F;
        #pragma unroll
        for (int nt = 0; nt < 8; nt++) {
            mt0 = fmaxf(mt0, fmaxf(s[nt][0], s[nt][1]));
            mt1 = fmaxf(mt1, fmaxf(s[nt][2], s[nt][3]));
        }
        #pragma unroll
        for (int off = 1; off < 4; off <<= 1) {
            mt0 = fmaxf(mt0, __shfl_xor_sync(0xffffffffu, mt0, off));
            mt1 = fmaxf(mt1, __shfl_xor_sync(0xffffffffu, mt1, off));
        }
        float mn0 = fmaxf(m0, mt0), mn1 = fmaxf(m1, mt1);
        float cor0 = __expf(m0 - mn0), cor1 = __expf(m1 - mn1);
        float rs0 = 0.f, rs1 = 0.f;
        #pragma unroll
        for (int nt = 0; nt < 8; nt++) {
            float p00 = __expf(s[nt][0] - mn0);
            float p01 = __expf(s[nt][1] - mn0);
            float p10 = __expf(s[nt][2] - mn1);
            float p11 = __expf(s[nt][3] - mn1);
            rs0 += p00 + p01; rs1 += p10 + p11;
            sts32(pst0 + 16u*nt, h2u(__floats2half2_rn(p00, p01)));
            sts32(pst1 + 16u*nt, h2u(__floats2half2_rn(p10, p11)));
        }
        #pragma unroll
        for (int off = 1; off < 4; off <<= 1) {
            rs0 += __shfl_xor_sync(0xffffffffu, rs0, off);
            rs1 += __shfl_xor_sync(0xffffffffu, rs1, off);
        }
        l0 = l0 * cor0 + rs0; m0 = mn0;
        l1 = l1 * cor1 + rs1; m1 = mn1;
        #pragma unroll
        for (int ct = 0; ct < 16; ct++) {
            o[ct][0] *= cor0; o[ct][1] *= cor0;
            o[ct][2] *= cor1; o[ct][3] *= cor1;
        }
        __syncwarp();

        // ---- O += P V ----
        const uint32_t vB = sb + 2u*(OFF_V + (t & 1)*C_*SVh + brow*SVh + bcol);
        #pragma unroll
        for (int kc = 0; kc < 4; kc++) {
            uint32_t a0,a1,a2,a3;
            ldsm4(a0,a1,a2,a3, aP + 32u*kc);
            #pragma unroll
            for (int np = 0; np < 8; np++) {
                uint32_t b0,b1,b2,b3;
                ldsm4(b0,b1,b2,b3, vB + 2u*(np*16*SVh + kc*16));
                mma16(o[2*np],   a0,a1,a2,a3, b0,b1);
                mma16(o[2*np+1], a0,a1,a2,a3, b2,b3);
            }
        }
    }

    // ---- epilogue: out = gamma * O/l + x * se ----
    const float gam = gamma[0];
    const float inv0 = 1.f / l0, inv1 = 1.f / l1;
    const int ir0 = i0 + warp*16 + quad, ir1 = ir0 + 8;
    #pragma unroll
    for (int ct = 0; ct < 16; ct++) {
        int c0 = ct*8 + qt*2;
        float se0 = g_se[b*C_ + c0], se1 = g_se[b*C_ + c0 + 1];
        size_t base0 = bcn + (size_t)c0 * N_;
        size_t base1 = base0 + N_;
        out[base0 + ir0] = gam * o[ct][0] * inv0 + x[base0 + ir0] * se0;
        out[base1 + ir0] = gam * o[ct][1] * inv0 + x[base1 + ir0] * se1;
        out[base0 + ir1] = gam * o[ct][2] * inv1 + x[base0 + ir1] * se0;
        out[base1 + ir1] = gam * o[ct][3] * inv1 + x[base1 + ir1] * se1;
    }
}

// ---------------------------------------------------------------------------
extern "C" void kernel_launch(void* const* d_in, const int* in_sizes, int n_in,
                              void* d_out, int out_size)
{
    const float* x     = (const float*)d_in[0];
    const float* Wq    = (const float*)d_in[1];
    const float* bq    = (const float*)d_in[2];
    const float* Wk    = (const float*)d_in[3];
    const float* bk    = (const float*)d_in[4];
    const float* Wv    = (const float*)d_in[5];
    const float* bv    = (const float*)d_in[6];
    const float* se_w1 = (const float*)d_in[7];
    const float* se_w2 = (const float*)d_in[8];
    const float* gamma = (const float*)d_in[9];
    float* out = (float*)d_out;

    static int smem_set = 0;
    if (!smem_set) {
        cudaFuncSetAttribute(attn_kernel,
                             cudaFuncAttributeMaxDynamicSharedMemorySize,
                             SMEM_HALFS * (int)sizeof(__half));
        cudaFuncSetAttribute(qkv_mma_kernel,
                             cudaFuncAttributeMaxDynamicSharedMemorySize,
                             QKV_SMEM_HALFS * (int)sizeof(__half));
        smem_set = 1;
    }

    prep_kernel<<<(W2_TOTAL + 255)/256, 256>>>(Wq, Wk, Wv);
    qkv_mma_kernel<<<dim3(N_/128, B_), 256, QKV_SMEM_HALFS * sizeof(__half)>>>(x, bq, bk, bv);
    se_reduce_kernel<<<B_*C_, 256>>>(x);
    se_mlp_kernel<<<1, 256>>>(se_w1, se_w2);
    attn_kernel<<<dim3(N_/BM, B_), 128, SMEM_HALFS * sizeof(__half)>>>(x, gamma, out);
}

// round 8
// speedup vs baseline: 1.8831x; 1.1552x over previous
#include <cuda_runtime.h>
#include <cuda_fp16.h>
#include <math_constants.h>
#include <cstdint>

#define B_ 8
#define C_ 128
#define N_ 2304
#define BM 64
#define BN 64
#define LOG2E 1.4426950408889634f

// ---------------- attention smem strides (halfs) ----------------
#define SQh 136
#define SKh 136
#define SVh 72
#define OFF_Q 0                           // 64*136  = 8704
#define OFF_K (BM*SQh)                    // 2*64*136 = 17408
#define OFF_V (OFF_K + 2*BN*SKh)          // 2*128*72 = 18432
#define SMEM_HALFS (OFF_V + 2*C_*SVh)     // 44544 halfs = 89088 B

// ---------------- qkv smem strides (halfs) ----------------
#define SX 136
#define SW 136
#define ST 136
#define QOFF_X  0
#define QOFF_W0 (C_*SX)
#define QOFF_W1 (QOFF_W0 + C_*SW)
#define QOFF_T  (QOFF_W1 + C_*SW)
#define QKV_SMEM_HALFS (QOFF_T + C_*ST)

__device__ __half g_qh[B_*N_*C_];   // [b][n][c]  (q pre-scaled by log2e)
__device__ __half g_kh[B_*N_*C_];   // [b][n][c]
__device__ __half g_vh[B_*C_*N_];   // [b][c][n]
__device__ __half g_wh[3*C_*C_];    // [which][o][c]
__device__ float  g_ymean[B_*C_];

// ---------------------------------------------------------------------------
__device__ __forceinline__ void cpa16(uint32_t s, const void* g){
    asm volatile("cp.async.cg.shared.global [%0], [%1], 16;" :: "r"(s), "l"(g));
}
__device__ __forceinline__ void cp_commit(){ asm volatile("cp.async.commit_group;"); }
__device__ __forceinline__ void cp_wait1(){ asm volatile("cp.async.wait_group 1;"); }
__device__ __forceinline__ void cp_wait0(){ asm volatile("cp.async.wait_group 0;"); }

__device__ __forceinline__ void ldsm4(uint32_t& r0,uint32_t& r1,uint32_t& r2,uint32_t& r3,
                                      uint32_t a){
    asm volatile("ldmatrix.sync.aligned.m8n8.x4.shared.b16 {%0,%1,%2,%3}, [%4];"
        : "=r"(r0),"=r"(r1),"=r"(r2),"=r"(r3) : "r"(a));
}
__device__ __forceinline__ void ldsm4t(uint32_t& r0,uint32_t& r1,uint32_t& r2,uint32_t& r3,
                                       uint32_t a){
    asm volatile("ldmatrix.sync.aligned.m8n8.x4.trans.shared.b16 {%0,%1,%2,%3}, [%4];"
        : "=r"(r0),"=r"(r1),"=r"(r2),"=r"(r3) : "r"(a));
}
__device__ __forceinline__ void stsm4t(uint32_t a, uint32_t r0,uint32_t r1,uint32_t r2,uint32_t r3){
    asm volatile("stmatrix.sync.aligned.m8n8.x4.trans.shared.b16 [%0], {%1,%2,%3,%4};"
        :: "r"(a), "r"(r0), "r"(r1), "r"(r2), "r"(r3));
}
__device__ __forceinline__ void sts32(uint32_t a, uint32_t v){
    asm volatile("st.shared.b32 [%0], %1;" :: "r"(a), "r"(v));
}
__device__ __forceinline__ void mma16(float* d, uint32_t a0,uint32_t a1,uint32_t a2,uint32_t a3,
                                      uint32_t b0,uint32_t b1){
    asm volatile(
      "mma.sync.aligned.m16n8k16.row.col.f32.f16.f16.f32 "
      "{%0,%1,%2,%3}, {%4,%5,%6,%7}, {%8,%9}, {%0,%1,%2,%3};"
      : "+f"(d[0]), "+f"(d[1]), "+f"(d[2]), "+f"(d[3])
      : "r"(a0), "r"(a1), "r"(a2), "r"(a3), "r"(b0), "r"(b1));
}
__device__ __forceinline__ uint32_t h2u(__half2 h){ return *reinterpret_cast<uint32_t*>(&h); }

// ---------------------------------------------------------------------------
// prep: fp32 -> fp16 for the 3 weight matrices
// ---------------------------------------------------------------------------
#define W2_TOTAL (3*C_*C_/2)
__global__ __launch_bounds__(256) void prep_kernel(
    const float* __restrict__ Wq,
    const float* __restrict__ Wk,
    const float* __restrict__ Wv)
{
    int idx = blockIdx.x * 256 + threadIdx.x;
    if (idx < W2_TOTAL) {
        int which = idx / (C_*C_/2);
        int r = idx - which * (C_*C_/2);
        const float* Wm = (which == 0) ? Wq : (which == 1) ? Wk : Wv;
        float2 v = ((const float2*)Wm)[r];
        ((__half2*)g_wh)[idx] = __floats2half2_rn(v.x, v.y);
    }
}

// ---------------------------------------------------------------------------
// QKV via fp16 tensor cores; x converted fp32->fp16 inline while staging.
// q/k epilogue transposed via stmatrix.trans. q scaled by log2e.
// grid (N/128, B), block 256 (8 warps).
// ---------------------------------------------------------------------------
__global__ void __launch_bounds__(256, 1) qkv_mma_kernel(
    const float* __restrict__ x,
    const float* __restrict__ bq,
    const float* __restrict__ bk,
    const float* __restrict__ bv)
{
    extern __shared__ __half smh[];
    uint32_t sb = (uint32_t)__cvta_generic_to_shared(smh);

    const int tid  = threadIdx.x;
    const int b    = blockIdx.y;
    const int n0   = blockIdx.x * 128;
    const int warp = tid >> 5, lane = tid & 31;
    const int quad = lane >> 2, qt = lane & 3;

    const float* xb = x + (size_t)b * C_ * N_;

    #pragma unroll
    for (int c2 = 0; c2 < 8; c2++) {
        int ch = tid + c2*256;
        int o = ch >> 4, cb = ch & 15;
        cpa16(sb + 2u*(QOFF_W0 + o*SW + cb*8), g_wh + o*C_ + cb*8);
    }
    cp_commit();

    #pragma unroll
    for (int c2 = 0; c2 < 8; c2++) {
        int ch = tid + c2*256;
        int c = ch >> 4, nb = ch & 15;
        const float* src = xb + (size_t)c*N_ + n0 + nb*8;
        float4 v0 = *(const float4*)src;
        float4 v1 = *(const float4*)(src + 4);
        uint4 hv;
        hv.x = h2u(__floats2half2_rn(v0.x, v0.y));
        hv.y = h2u(__floats2half2_rn(v0.z, v0.w));
        hv.z = h2u(__floats2half2_rn(v1.x, v1.y));
        hv.w = h2u(__floats2half2_rn(v1.z, v1.w));
        *(uint4*)&smh[QOFF_X + c*SX + nb*8] = hv;
    }
    cp_wait0();
    __syncthreads();

    #pragma unroll
    for (int c2 = 0; c2 < 8; c2++) {
        int ch = tid + c2*256;
        int o = ch >> 4, cb = ch & 15;
        cpa16(sb + 2u*(QOFF_W1 + o*SW + cb*8), g_wh + C_*C_ + o*C_ + cb*8);
    }
    cp_commit();

    const int r16 = lane & 15;
    const int hi8 = (lane >> 4) * 8;
    const uint32_t bX = sb + 2u*(QOFF_X + r16*SX + hi8);
    // stmatrix (transposed [n][o]) base for q/k epilogue
    const int smm = lane >> 3, smr = lane & 7;
    const uint32_t stb = sb + 2u*(QOFF_T + ((smm>>1)*8 + smr)*ST + warp*16 + (smm&1)*8);
    // sts32 base ([o][n]) for v epilogue
    const uint32_t tst0 = sb + 2u*(QOFF_T + (warp*16 + quad)*ST + qt*2);
    const uint32_t tst1 = tst0 + 2u*8*ST;

    const int o_r0 = warp*16 + quad, o_r1 = o_r0 + 8;

    #pragma unroll
    for (int which = 0; which < 3; which++) {
        const uint32_t wbuf = sb + 2u*((which & 1) ? QOFF_W1 : QOFF_W0);
        const uint32_t aW = wbuf + 2u*((warp*16 + r16)*SW + hi8);

        float acc[16][4];
        #pragma unroll
        for (int nt = 0; nt < 16; nt++)
            #pragma unroll
            for (int r = 0; r < 4; r++) acc[nt][r] = 0.f;

        #pragma unroll
        for (int kc = 0; kc < 8; kc++) {
            uint32_t a0,a1,a2,a3;
            ldsm4(a0,a1,a2,a3, aW + 32u*kc);
            #pragma unroll
            for (int nt16 = 0; nt16 < 8; nt16++) {
                uint32_t b0,b1,b2,b3;
                ldsm4t(b0,b1,b2,b3, bX + 2u*(kc*16*SX + nt16*16));
                mma16(acc[2*nt16],   a0,a1,a2,a3, b0,b1);
                mma16(acc[2*nt16+1], a0,a1,a2,a3, b2,b3);
            }
        }

        const float* bias = (which == 0) ? bq : (which == 1) ? bk : bv;
        const float sc = (which == 0) ? LOG2E : 1.0f;
        float b0f = bias[o_r0], b1f = bias[o_r1];

        if (which < 2) {
            // pack + stmatrix-transpose into Ts[n][o]
            #pragma unroll
            for (int nt16 = 0; nt16 < 8; nt16++) {
                uint32_t r0 = h2u(__floats2half2_rn((acc[2*nt16][0]+b0f)*sc,   (acc[2*nt16][1]+b0f)*sc));
                uint32_t r1 = h2u(__floats2half2_rn((acc[2*nt16][2]+b1f)*sc,   (acc[2*nt16][3]+b1f)*sc));
                uint32_t r2 = h2u(__floats2half2_rn((acc[2*nt16+1][0]+b0f)*sc, (acc[2*nt16+1][1]+b0f)*sc));
                uint32_t r3 = h2u(__floats2half2_rn((acc[2*nt16+1][2]+b1f)*sc, (acc[2*nt16+1][3]+b1f)*sc));
                stsm4t(stb + 2u*(nt16*16*ST), r0, r1, r2, r3);
            }
            __syncthreads();
            if (which == 0) {
                #pragma unroll
                for (int c2 = 0; c2 < 8; c2++) {
                    int ch = tid + c2*256;
                    int o = ch >> 4, cb = ch & 15;
                    cpa16(sb + 2u*(QOFF_W0 + o*SW + cb*8), g_wh + 2*C_*C_ + o*C_ + cb*8);
                }
                cp_commit();
            }
            __half* dsth = (which == 0) ? g_qh : g_kh;
            #pragma unroll
            for (int c2 = 0; c2 < 8; c2++) {
                int ch = tid + c2*256;
                int n = ch >> 4, ob = ch & 15;
                uint4 v = *(uint4*)&smh[QOFF_T + n*ST + ob*8];
                *(uint4*)(dsth + ((size_t)b*N_ + n0 + n)*C_ + ob*8) = v;
            }
            cp_wait0();
            __syncthreads();
        } else {
            // v: [o][n] direct via sts32
            #pragma unroll
            for (int nt = 0; nt < 16; nt++) {
                sts32(tst0 + 16u*nt, h2u(__floats2half2_rn(acc[nt][0] + b0f, acc[nt][1] + b0f)));
                sts32(tst1 + 16u*nt, h2u(__floats2half2_rn(acc[nt][2] + b1f, acc[nt][3] + b1f)));
            }
            __syncthreads();
            #pragma unroll
            for (int c2 = 0; c2 < 8; c2++) {
                int ch = tid + c2*256;
                int o = ch >> 4, nb = ch & 15;
                uint4 v = *(uint4*)&smh[QOFF_T + o*ST + nb*8];
                *(uint4*)(g_vh + ((size_t)b*C_ + o)*N_ + n0 + nb*8) = v;
            }
        }
    }
}

// ---------------------------------------------------------------------------
// SE mean reduction: one CTA per (b,c) row
// ---------------------------------------------------------------------------
__global__ __launch_bounds__(256) void se_reduce_kernel(const float* __restrict__ x)
{
    int bc = blockIdx.x;
    const float* row = x + (size_t)bc * N_;
    int tid = threadIdx.x;
    float s = 0.f;
    for (int n = tid; n < N_; n += 256) s += row[n];
    __shared__ float red[8];
    #pragma unroll
    for (int off = 16; off > 0; off >>= 1)
        s += __shfl_xor_sync(0xffffffffu, s, off);
    if ((tid & 31) == 0) red[tid >> 5] = s;
    __syncthreads();
    if (tid < 8) {
        float v = red[tid];
        #pragma unroll
        for (int off = 4; off > 0; off >>= 1)
            v += __shfl_xor_sync(0xffu, v, off);
        if (tid == 0) g_ymean[bc] = v / (float)N_;
    }
}

// ---------------------------------------------------------------------------
// Flash attention: BM=64, 4 warps, 2 CTAs/SM. fp16 MMA, P in registers,
// exp2-domain softmax, SE MLP computed in-CTA, fused combine.
// grid (N/64, B), block 128.
// ---------------------------------------------------------------------------
__global__ void __launch_bounds__(128, 2) attn_kernel(
    const float* __restrict__ x,
    const float* __restrict__ gamma,
    const float* __restrict__ w1,
    const float* __restrict__ w2,
    float* __restrict__ out)
{
    extern __shared__ __half smh[];
    uint32_t sb = (uint32_t)__cvta_generic_to_shared(smh);
    __shared__ float ym[C_];
    __shared__ float y1_sh[8];
    __shared__ float se_sh[C_];

    const int tid  = threadIdx.x;
    const int b    = blockIdx.y;
    const int i0   = blockIdx.x * BM;
    const int warp = tid >> 5, lane = tid & 31;
    const int quad = lane >> 2, qt = lane & 3;

    const size_t bcn = (size_t)b * C_ * N_;
    const __half* qb = g_qh + (size_t)b * N_ * C_;
    const __half* kb = g_kh + (size_t)b * N_ * C_;
    const __half* vb = g_vh + (size_t)b * C_ * N_;

    // ---- prologue: group A = (Q, K0, V0); group B = (K1, V1) ----
    #pragma unroll
    for (int c2 = 0; c2 < 8; c2++) {
        int ch = tid + c2*128;
        int i = ch >> 4, cb = ch & 15;
        cpa16(sb + 2u*(OFF_Q + i*SQh + cb*8), qb + (size_t)(i0 + i)*C_ + cb*8);
    }
    #pragma unroll
    for (int c2 = 0; c2 < 8; c2++) {
        int ch = tid + c2*128;
        int j = ch >> 4, cb = ch & 15;
        cpa16(sb + 2u*(OFF_K + j*SKh + cb*8), kb + (size_t)j*C_ + cb*8);
    }
    #pragma unroll
    for (int c2 = 0; c2 < 8; c2++) {
        int ch = tid + c2*128;
        int c = ch >> 3, cb = ch & 7;
        cpa16(sb + 2u*(OFF_V + c*SVh + cb*8), vb + (size_t)c*N_ + cb*8);
    }
    cp_commit();
    #pragma unroll
    for (int c2 = 0; c2 < 8; c2++) {
        int ch = tid + c2*128;
        int j = ch >> 4, cb = ch & 15;
        cpa16(sb + 2u*(OFF_K + BN*SKh + j*SKh + cb*8), kb + (size_t)(BN + j)*C_ + cb*8);
    }
    #pragma unroll
    for (int c2 = 0; c2 < 8; c2++) {
        int ch = tid + c2*128;
        int c = ch >> 3, cb = ch & 7;
        cpa16(sb + 2u*(OFF_V + C_*SVh + c*SVh + cb*8), vb + (size_t)c*N_ + BN + cb*8);
    }
    cp_commit();

    // ---- SE MLP (overlapped with prologue cp.async) ----
    ym[tid] = g_ymean[b*C_ + tid];
    __syncthreads();
    if (tid < 8) {
        float a = 0.f;
        #pragma unroll 8
        for (int c = 0; c < C_; c++) a += w1[tid*C_ + c] * ym[c];
        y1_sh[tid] = fmaxf(a, 0.f);
    }
    __syncthreads();
    {
        float a = 0.f;
        #pragma unroll
        for (int r = 0; r < 8; r++) a += w2[tid*8 + r] * y1_sh[r];
        se_sh[tid] = 1.f / (1.f + __expf(-a));
    }

    cp_wait1();
    __syncthreads();

    float o[16][4];
    #pragma unroll
    for (int ct = 0; ct < 16; ct++)
        #pragma unroll
        for (int r = 0; r < 4; r++) o[ct][r] = 0.f;
    float m0 = -CUDART_INF_F, m1 = -CUDART_INF_F, l0 = 0.f, l1 = 0.f;

    const int r16  = lane & 15;
    const int ahi  = (lane >> 4) * 8;
    const int brow = (lane & 7) + ((lane >> 4) & 1) * 8;
    const int bcol = ((lane >> 3) & 1) * 8;

    const uint32_t aQ = sb + 2u*(OFF_Q + (warp*16 + r16)*SQh + ahi);

    for (int t = 0; t < 36; t++) {
        if (t > 0) {
            cp_wait0();
            __syncthreads();
            if (t < 35) {
                const int jn = (t + 1) * BN;
                const uint32_t kdst = sb + 2u*(OFF_K + ((t+1)&1)*BN*SKh);
                const uint32_t vdst = sb + 2u*(OFF_V + ((t+1)&1)*C_*SVh);
                #pragma unroll
                for (int c2 = 0; c2 < 8; c2++) {
                    int ch = tid + c2*128;
                    int j = ch >> 4, cb = ch & 15;
                    cpa16(kdst + 2u*(j*SKh + cb*8), kb + (size_t)(jn + j)*C_ + cb*8);
                }
                #pragma unroll
                for (int c2 = 0; c2 < 8; c2++) {
                    int ch = tid + c2*128;
                    int c = ch >> 3, cb = ch & 7;
                    cpa16(vdst + 2u*(c*SVh + cb*8), vb + (size_t)c*N_ + jn + cb*8);
                }
                cp_commit();
            }
        }

        // ---- S = Q K^T  (log2 domain: q pre-scaled by log2e) ----
        float s[8][4];
        #pragma unroll
        for (int nt = 0; nt < 8; nt++)
            #pragma unroll
            for (int r = 0; r < 4; r++) s[nt][r] = 0.f;

        const uint32_t kB = sb + 2u*(OFF_K + (t & 1)*BN*SKh + brow*SKh + bcol);
        #pragma unroll
        for (int kc = 0; kc < 8; kc++) {
            uint32_t a0,a1,a2,a3;
            ldsm4(a0,a1,a2,a3, aQ + 32u*kc);
            #pragma unroll
            for (int np = 0; np < 4; np++) {
                uint32_t b0,b1,b2,b3;
                ldsm4(b0,b1,b2,b3, kB + 2u*(np*16*SKh + kc*16));
                mma16(s[2*np],   a0,a1,a2,a3, b0,b1);
                mma16(s[2*np+1], a0,a1,a2,a3, b2,b3);
            }
        }

        // ---- online softmax (exp2); P packed into A-fragment registers ----
        float mt0 = -CUDART_INF_F, mt1 = -CUDART_INF_F;
        #pragma unroll
        for (int nt = 0; nt < 8; nt++) {
            mt0 = fmaxf(mt0, fmaxf(s[nt][0], s[nt][1]));
            mt1 = fmaxf(mt1, fmaxf(s[nt][2], s[nt][3]));
        }
        #pragma unroll
        for (int off = 1; off < 4; off <<= 1) {
            mt0 = fmaxf(mt0, __shfl_xor_sync(0xffffffffu, mt0, off));
            mt1 = fmaxf(mt1, __shfl_xor_sync(0xffffffffu, mt1, off));
        }
        float mn0 = fmaxf(m0, mt0), mn1 = fmaxf(m1, mt1);
        float cor0 = exp2f(m0 - mn0), cor1 = exp2f(m1 - mn1);
        float rs0 = 0.f, rs1 = 0.f;
        uint32_t pa0[8], pa1[8];
        #pragma unroll
        for (int nt = 0; nt < 8; nt++) {
            float p00 = exp2f(s[nt][0] - mn0);
            float p01 = exp2f(s[nt][1] - mn0);
            float p10 = exp2f(s[nt][2] - mn1);
            float p11 = exp2f(s[nt][3] - mn1);
            rs0 += p00 + p01; rs1 += p10 + p11;
            pa0[nt] = h2u(__floats2half2_rn(p00, p01));   // rows 0-7 half
            pa1[nt] = h2u(__floats2half2_rn(p10, p11));   // rows 8-15 half
        }
        #pragma unroll
        for (int off = 1; off < 4; off <<= 1) {
            rs0 += __shfl_xor_sync(0xffffffffu, rs0, off);
            rs1 += __shfl_xor_sync(0xffffffffu, rs1, off);
        }
        l0 = l0 * cor0 + rs0; m0 = mn0;
        l1 = l1 * cor1 + rs1; m1 = mn1;
        #pragma unroll
        for (int ct = 0; ct < 16; ct++) {
            o[ct][0] *= cor0; o[ct][1] *= cor0;
            o[ct][2] *= cor1; o[ct][3] *= cor1;
        }

        // ---- O += P V  (A from registers) ----
        const uint32_t vB = sb + 2u*(OFF_V + (t & 1)*C_*SVh + brow*SVh + bcol);
        #pragma unroll
        for (int kc = 0; kc < 4; kc++) {
            uint32_t a0 = pa0[2*kc],   a1 = pa1[2*kc];
            uint32_t a2 = pa0[2*kc+1], a3 = pa1[2*kc+1];
            #pragma unroll
            for (int np = 0; np < 8; np++) {
                uint32_t b0,b1,b2,b3;
                ldsm4(b0,b1,b2,b3, vB + 2u*(np*16*SVh + kc*16));
                mma16(o[2*np],   a0,a1,a2,a3, b0,b1);
                mma16(o[2*np+1], a0,a1,a2,a3, b2,b3);
            }
        }
    }

    // ---- epilogue: out = gamma * O/l + x * se ----
    const float gam = gamma[0];
    const float inv0 = 1.f / l0, inv1 = 1.f / l1;
    const int ir0 = i0 + warp*16 + quad, ir1 = ir0 + 8;
    #pragma unroll
    for (int ct = 0; ct < 16; ct++) {
        int c0 = ct*8 + qt*2;
        float se0 = se_sh[c0], se1 = se_sh[c0 + 1];
        size_t base0 = bcn + (size_t)c0 * N_;
        size_t base1 = base0 + N_;
        out[base0 + ir0] = gam * o[ct][0] * inv0 + x[base0 + ir0] * se0;
        out[base1 + ir0] = gam * o[ct][1] * inv0 + x[base1 + ir0] * se1;
        out[base0 + ir1] = gam * o[ct][2] * inv1 + x[base0 + ir1] * se0;
        out[base1 + ir1] = gam * o[ct][3] * inv1 + x[base1 + ir1] * se1;
    }
}

// ---------------------------------------------------------------------------
extern "C" void kernel_launch(void* const* d_in, const int* in_sizes, int n_in,
                              void* d_out, int out_size)
{
    const float* x     = (const float*)d_in[0];
    const float* Wq    = (const float*)d_in[1];
    const float* bq    = (const float*)d_in[2];
    const float* Wk    = (const float*)d_in[3];
    const float* bk    = (const float*)d_in[4];
    const float* Wv    = (const float*)d_in[5];
    const float* bv    = (const float*)d_in[6];
    const float* se_w1 = (const float*)d_in[7];
    const float* se_w2 = (const float*)d_in[8];
    const float* gamma = (const float*)d_in[9];
    float* out = (float*)d_out;

    static int smem_set = 0;
    if (!smem_set) {
        cudaFuncSetAttribute(attn_kernel,
                             cudaFuncAttributeMaxDynamicSharedMemorySize,
                             SMEM_HALFS * (int)sizeof(__half));
        cudaFuncSetAttribute(qkv_mma_kernel,
                             cudaFuncAttributeMaxDynamicSharedMemorySize,
                             QKV_SMEM_HALFS * (int)sizeof(__half));
        smem_set = 1;
    }

    prep_kernel<<<(W2_TOTAL + 255)/256, 256>>>(Wq, Wk, Wv);
    qkv_mma_kernel<<<dim3(N_/128, B_), 256, QKV_SMEM_HALFS * sizeof(__half)>>>(x, bq, bk, bv);
    se_reduce_kernel<<<B_*C_, 256>>>(x);
    attn_kernel<<<dim3(N_/BM, B_), 128, SMEM_HALFS * sizeof(__half)>>>(x, gamma, se_w1, se_w2, out);
}

// round 9
// speedup vs baseline: 1.9312x; 1.0256x over previous
#include <cuda_runtime.h>
#include <cuda_fp16.h>
#include <math_constants.h>
#include <cstdint>

#define B_ 8
#define C_ 128
#define N_ 2304
#define BM 64
#define BN 64
#define NTILE 18
#define LOG2E 1.4426950408889634f

// ---------------- attention smem strides (halfs) ----------------
#define SQh 136
#define SKh 136
#define SVh 72
#define OFF_Q 0
#define OFF_K (BM*SQh)
#define OFF_V (OFF_K + 2*BN*SKh)
#define SMEM_HALFS (OFF_V + 2*C_*SVh)     // 44544 halfs = 89088 B

// ---------------- qkv smem strides (halfs) ----------------
#define SX 136
#define SW 136
#define ST 136
#define QOFF_X  0
#define QOFF_W0 (C_*SX)
#define QOFF_W1 (QOFF_W0 + C_*SW)
#define QOFF_T  (QOFF_W1 + C_*SW)
#define QKV_SMEM_HALFS (QOFF_T + C_*ST)

__device__ __half g_qh[B_*N_*C_];   // [b][n][c]  (q pre-scaled by log2e)
__device__ __half g_kh[B_*N_*C_];   // [b][n][c]
__device__ __half g_vh[B_*C_*N_];   // [b][c][n]
__device__ __half g_wh[3*C_*C_];    // [which][o][c]
__device__ float  g_ypart[B_*NTILE*C_];

// ---------------------------------------------------------------------------
__device__ __forceinline__ void cpa16(uint32_t s, const void* g){
    asm volatile("cp.async.cg.shared.global [%0], [%1], 16;" :: "r"(s), "l"(g));
}
__device__ __forceinline__ void cp_commit(){ asm volatile("cp.async.commit_group;"); }
__device__ __forceinline__ void cp_wait1(){ asm volatile("cp.async.wait_group 1;"); }
__device__ __forceinline__ void cp_wait0(){ asm volatile("cp.async.wait_group 0;"); }

__device__ __forceinline__ void ldsm4(uint32_t& r0,uint32_t& r1,uint32_t& r2,uint32_t& r3,
                                      uint32_t a){
    asm volatile("ldmatrix.sync.aligned.m8n8.x4.shared.b16 {%0,%1,%2,%3}, [%4];"
        : "=r"(r0),"=r"(r1),"=r"(r2),"=r"(r3) : "r"(a));
}
__device__ __forceinline__ void ldsm4t(uint32_t& r0,uint32_t& r1,uint32_t& r2,uint32_t& r3,
                                       uint32_t a){
    asm volatile("ldmatrix.sync.aligned.m8n8.x4.trans.shared.b16 {%0,%1,%2,%3}, [%4];"
        : "=r"(r0),"=r"(r1),"=r"(r2),"=r"(r3) : "r"(a));
}
__device__ __forceinline__ void stsm4t(uint32_t a, uint32_t r0,uint32_t r1,uint32_t r2,uint32_t r3){
    asm volatile("stmatrix.sync.aligned.m8n8.x4.trans.shared.b16 [%0], {%1,%2,%3,%4};"
        :: "r"(a), "r"(r0), "r"(r1), "r"(r2), "r"(r3));
}
__device__ __forceinline__ void sts32(uint32_t a, uint32_t v){
    asm volatile("st.shared.b32 [%0], %1;" :: "r"(a), "r"(v));
}
__device__ __forceinline__ void mma16(float* d, uint32_t a0,uint32_t a1,uint32_t a2,uint32_t a3,
                                      uint32_t b0,uint32_t b1){
    asm volatile(
      "mma.sync.aligned.m16n8k16.row.col.f32.f16.f16.f32 "
      "{%0,%1,%2,%3}, {%4,%5,%6,%7}, {%8,%9}, {%0,%1,%2,%3};"
      : "+f"(d[0]), "+f"(d[1]), "+f"(d[2]), "+f"(d[3])
      : "r"(a0), "r"(a1), "r"(a2), "r"(a3), "r"(b0), "r"(b1));
}
__device__ __forceinline__ uint32_t h2u(__half2 h){ return *reinterpret_cast<uint32_t*>(&h); }
__device__ __forceinline__ float ex2f(float x){
    float y; asm("ex2.approx.f32 %0, %1;" : "=f"(y) : "f"(x)); return y;
}

// ---------------------------------------------------------------------------
// prep: fp32 -> fp16 for the 3 weight matrices
// ---------------------------------------------------------------------------
#define W2_TOTAL (3*C_*C_/2)
__global__ __launch_bounds__(256) void prep_kernel(
    const float* __restrict__ Wq,
    const float* __restrict__ Wk,
    const float* __restrict__ Wv)
{
    int idx = blockIdx.x * 256 + threadIdx.x;
    if (idx < W2_TOTAL) {
        int which = idx / (C_*C_/2);
        int r = idx - which * (C_*C_/2);
        const float* Wm = (which == 0) ? Wq : (which == 1) ? Wk : Wv;
        float2 v = ((const float2*)Wm)[r];
        ((__half2*)g_wh)[idx] = __floats2half2_rn(v.x, v.y);
    }
}

// ---------------------------------------------------------------------------
// QKV via fp16 tensor cores; x converted fp32->fp16 inline while staging.
// Also emits per-tile channel sums for the SE branch (g_ypart).
// grid (N/128, B), block 256 (8 warps).
// ---------------------------------------------------------------------------
__global__ void __launch_bounds__(256, 1) qkv_mma_kernel(
    const float* __restrict__ x,
    const float* __restrict__ bq,
    const float* __restrict__ bk,
    const float* __restrict__ bv)
{
    extern __shared__ __half smh[];
    uint32_t sb = (uint32_t)__cvta_generic_to_shared(smh);

    const int tid  = threadIdx.x;
    const int b    = blockIdx.y;
    const int n0   = blockIdx.x * 128;
    const int warp = tid >> 5, lane = tid & 31;
    const int quad = lane >> 2, qt = lane & 3;

    const float* xb = x + (size_t)b * C_ * N_;

    #pragma unroll
    for (int c2 = 0; c2 < 8; c2++) {
        int ch = tid + c2*256;
        int o = ch >> 4, cb = ch & 15;
        cpa16(sb + 2u*(QOFF_W0 + o*SW + cb*8), g_wh + o*C_ + cb*8);
    }
    cp_commit();

    #pragma unroll
    for (int c2 = 0; c2 < 8; c2++) {
        int ch = tid + c2*256;
        int c = ch >> 4, nb = ch & 15;
        const float* src = xb + (size_t)c*N_ + n0 + nb*8;
        float4 v0 = *(const float4*)src;
        float4 v1 = *(const float4*)(src + 4);
        uint4 hv;
        hv.x = h2u(__floats2half2_rn(v0.x, v0.y));
        hv.y = h2u(__floats2half2_rn(v0.z, v0.w));
        hv.z = h2u(__floats2half2_rn(v1.x, v1.y));
        hv.w = h2u(__floats2half2_rn(v1.z, v1.w));
        *(uint4*)&smh[QOFF_X + c*SX + nb*8] = hv;
    }
    cp_wait0();
    __syncthreads();

    #pragma unroll
    for (int c2 = 0; c2 < 8; c2++) {
        int ch = tid + c2*256;
        int o = ch >> 4, cb = ch & 15;
        cpa16(sb + 2u*(QOFF_W1 + o*SW + cb*8), g_wh + C_*C_ + o*C_ + cb*8);
    }
    cp_commit();

    // ---- SE partial: per-channel sum of this x tile (fp16 smem) ----
    if (tid < C_) {
        const uint4* row = (const uint4*)&smh[QOFF_X + tid*SX];
        float s = 0.f;
        #pragma unroll
        for (int u = 0; u < 16; u++) {
            uint4 v = row[u];
            float2 f0 = __half22float2(*(__half2*)&v.x);
            float2 f1 = __half22float2(*(__half2*)&v.y);
            float2 f2 = __half22float2(*(__half2*)&v.z);
            float2 f3 = __half22float2(*(__half2*)&v.w);
            s += (f0.x + f0.y) + (f1.x + f1.y) + (f2.x + f2.y) + (f3.x + f3.y);
        }
        g_ypart[((size_t)b*NTILE + blockIdx.x)*C_ + tid] = s;
    }

    const int r16 = lane & 15;
    const int hi8 = (lane >> 4) * 8;
    const uint32_t bX = sb + 2u*(QOFF_X + r16*SX + hi8);
    const int smm = lane >> 3, smr = lane & 7;
    const uint32_t stb = sb + 2u*(QOFF_T + ((smm>>1)*8 + smr)*ST + warp*16 + (smm&1)*8);
    const uint32_t tst0 = sb + 2u*(QOFF_T + (warp*16 + quad)*ST + qt*2);
    const uint32_t tst1 = tst0 + 2u*8*ST;

    const int o_r0 = warp*16 + quad, o_r1 = o_r0 + 8;

    #pragma unroll
    for (int which = 0; which < 3; which++) {
        const uint32_t wbuf = sb + 2u*((which & 1) ? QOFF_W1 : QOFF_W0);
        const uint32_t aW = wbuf + 2u*((warp*16 + r16)*SW + hi8);

        float acc[16][4];
        #pragma unroll
        for (int nt = 0; nt < 16; nt++)
            #pragma unroll
            for (int r = 0; r < 4; r++) acc[nt][r] = 0.f;

        #pragma unroll
        for (int kc = 0; kc < 8; kc++) {
            uint32_t a0,a1,a2,a3;
            ldsm4(a0,a1,a2,a3, aW + 32u*kc);
            #pragma unroll
            for (int nt16 = 0; nt16 < 8; nt16++) {
                uint32_t b0,b1,b2,b3;
                ldsm4t(b0,b1,b2,b3, bX + 2u*(kc*16*SX + nt16*16));
                mma16(acc[2*nt16],   a0,a1,a2,a3, b0,b1);
                mma16(acc[2*nt16+1], a0,a1,a2,a3, b2,b3);
            }
        }

        const float* bias = (which == 0) ? bq : (which == 1) ? bk : bv;
        const float sc = (which == 0) ? LOG2E : 1.0f;
        float b0f = bias[o_r0], b1f = bias[o_r1];

        if (which < 2) {
            #pragma unroll
            for (int nt16 = 0; nt16 < 8; nt16++) {
                uint32_t r0 = h2u(__floats2half2_rn((acc[2*nt16][0]+b0f)*sc,   (acc[2*nt16][1]+b0f)*sc));
                uint32_t r1 = h2u(__floats2half2_rn((acc[2*nt16][2]+b1f)*sc,   (acc[2*nt16][3]+b1f)*sc));
                uint32_t r2 = h2u(__floats2half2_rn((acc[2*nt16+1][0]+b0f)*sc, (acc[2*nt16+1][1]+b0f)*sc));
                uint32_t r3 = h2u(__floats2half2_rn((acc[2*nt16+1][2]+b1f)*sc, (acc[2*nt16+1][3]+b1f)*sc));
                stsm4t(stb + 2u*(nt16*16*ST), r0, r1, r2, r3);
            }
            __syncthreads();
            if (which == 0) {
                #pragma unroll
                for (int c2 = 0; c2 < 8; c2++) {
                    int ch = tid + c2*256;
                    int o = ch >> 4, cb = ch & 15;
                    cpa16(sb + 2u*(QOFF_W0 + o*SW + cb*8), g_wh + 2*C_*C_ + o*C_ + cb*8);
                }
                cp_commit();
            }
            __half* dsth = (which == 0) ? g_qh : g_kh;
            #pragma unroll
            for (int c2 = 0; c2 < 8; c2++) {
                int ch = tid + c2*256;
                int n = ch >> 4, ob = ch & 15;
                uint4 v = *(uint4*)&smh[QOFF_T + n*ST + ob*8];
                *(uint4*)(dsth + ((size_t)b*N_ + n0 + n)*C_ + ob*8) = v;
            }
            cp_wait0();
            __syncthreads();
        } else {
            #pragma unroll
            for (int nt = 0; nt < 16; nt++) {
                sts32(tst0 + 16u*nt, h2u(__floats2half2_rn(acc[nt][0] + b0f, acc[nt][1] + b0f)));
                sts32(tst1 + 16u*nt, h2u(__floats2half2_rn(acc[nt][2] + b1f, acc[nt][3] + b1f)));
            }
            __syncthreads();
            #pragma unroll
            for (int c2 = 0; c2 < 8; c2++) {
                int ch = tid + c2*256;
                int o = ch >> 4, nb = ch & 15;
                uint4 v = *(uint4*)&smh[QOFF_T + o*ST + nb*8];
                *(uint4*)(g_vh + ((size_t)b*C_ + o)*N_ + n0 + nb*8) = v;
            }
        }
    }
}

// ---------------------------------------------------------------------------
// Flash attention: BM=64, 4 warps, 2 CTAs/SM. fp16 MMA, P in registers,
// exp2-domain softmax (bare MUFU), skip-rescale, in-CTA SE MLP, fused combine.
// grid (N/64, B), block 128.
// ---------------------------------------------------------------------------
__global__ void __launch_bounds__(128, 2) attn_kernel(
    const float* __restrict__ x,
    const float* __restrict__ gamma,
    const float* __restrict__ w1,
    const float* __restrict__ w2,
    float* __restrict__ out)
{
    extern __shared__ __half smh[];
    uint32_t sb = (uint32_t)__cvta_generic_to_shared(smh);
    __shared__ float ym[C_];
    __shared__ float y1_sh[8];
    __shared__ float se_sh[C_];

    const int tid  = threadIdx.x;
    const int b    = blockIdx.y;
    const int i0   = blockIdx.x * BM;
    const int warp = tid >> 5, lane = tid & 31;
    const int quad = lane >> 2, qt = lane & 3;

    const size_t bcn = (size_t)b * C_ * N_;
    const __half* qb = g_qh + (size_t)b * N_ * C_;
    const __half* kb = g_kh + (size_t)b * N_ * C_;
    const __half* vb = g_vh + (size_t)b * C_ * N_;

    // ---- prologue: group A = (Q, K0, V0); group B = (K1, V1) ----
    #pragma unroll
    for (int c2 = 0; c2 < 8; c2++) {
        int ch = tid + c2*128;
        int i = ch >> 4, cb = ch & 15;
        cpa16(sb + 2u*(OFF_Q + i*SQh + cb*8), qb + (size_t)(i0 + i)*C_ + cb*8);
    }
    #pragma unroll
    for (int c2 = 0; c2 < 8; c2++) {
        int ch = tid + c2*128;
        int j = ch >> 4, cb = ch & 15;
        cpa16(sb + 2u*(OFF_K + j*SKh + cb*8), kb + (size_t)j*C_ + cb*8);
    }
    #pragma unroll
    for (int c2 = 0; c2 < 8; c2++) {
        int ch = tid + c2*128;
        int c = ch >> 3, cb = ch & 7;
        cpa16(sb + 2u*(OFF_V + c*SVh + cb*8), vb + (size_t)c*N_ + cb*8);
    }
    cp_commit();
    #pragma unroll
    for (int c2 = 0; c2 < 8; c2++) {
        int ch = tid + c2*128;
        int j = ch >> 4, cb = ch & 15;
        cpa16(sb + 2u*(OFF_K + BN*SKh + j*SKh + cb*8), kb + (size_t)(BN + j)*C_ + cb*8);
    }
    #pragma unroll
    for (int c2 = 0; c2 < 8; c2++) {
        int ch = tid + c2*128;
        int c = ch >> 3, cb = ch & 7;
        cpa16(sb + 2u*(OFF_V + C_*SVh + c*SVh + cb*8), vb + (size_t)c*N_ + BN + cb*8);
    }
    cp_commit();

    // ---- SE MLP (overlapped with prologue cp.async) ----
    {
        float acc = 0.f;
        #pragma unroll
        for (int tt = 0; tt < NTILE; tt++)
            acc += g_ypart[((size_t)b*NTILE + tt)*C_ + tid];
        ym[tid] = acc * (1.f / (float)N_);
    }
    __syncthreads();
    {
        // parallel w1 dot: 16 threads per hidden unit h = tid>>4
        int h = tid >> 4, cl = tid & 15;
        float p = 0.f;
        #pragma unroll
        for (int u = 0; u < 8; u++) {
            int c = cl + u*16;
            p += w1[h*C_ + c] * ym[c];
        }
        #pragma unroll
        for (int off = 1; off < 16; off <<= 1)
            p += __shfl_xor_sync(0xffffffffu, p, off);
        if (cl == 0) y1_sh[h] = fmaxf(p, 0.f);
    }
    __syncthreads();
    {
        float a = 0.f;
        #pragma unroll
        for (int r = 0; r < 8; r++) a += w2[tid*8 + r] * y1_sh[r];
        se_sh[tid] = 1.f / (1.f + ex2f(-a * LOG2E));
    }

    cp_wait1();
    __syncthreads();

    float o[16][4];
    #pragma unroll
    for (int ct = 0; ct < 16; ct++)
        #pragma unroll
        for (int r = 0; r < 4; r++) o[ct][r] = 0.f;
    float m0 = -CUDART_INF_F, m1 = -CUDART_INF_F, l0 = 0.f, l1 = 0.f;

    const int r16  = lane & 15;
    const int ahi  = (lane >> 4) * 8;
    const int brow = (lane & 7) + ((lane >> 4) & 1) * 8;
    const int bcol = ((lane >> 3) & 1) * 8;

    const uint32_t aQ = sb + 2u*(OFF_Q + (warp*16 + r16)*SQh + ahi);

    for (int t = 0; t < 36; t++) {
        if (t > 0) {
            cp_wait0();
            __syncthreads();
            if (t < 35) {
                const int jn = (t + 1) * BN;
                const uint32_t kdst = sb + 2u*(OFF_K + ((t+1)&1)*BN*SKh);
                const uint32_t vdst = sb + 2u*(OFF_V + ((t+1)&1)*C_*SVh);
                #pragma unroll
                for (int c2 = 0; c2 < 8; c2++) {
                    int ch = tid + c2*128;
                    int j = ch >> 4, cb = ch & 15;
                    cpa16(kdst + 2u*(j*SKh + cb*8), kb + (size_t)(jn + j)*C_ + cb*8);
                }
                #pragma unroll
                for (int c2 = 0; c2 < 8; c2++) {
                    int ch = tid + c2*128;
                    int c = ch >> 3, cb = ch & 7;
                    cpa16(vdst + 2u*(c*SVh + cb*8), vb + (size_t)c*N_ + jn + cb*8);
                }
                cp_commit();
            }
        }

        // ---- S = Q K^T  (log2 domain) ----
        float s[8][4];
        #pragma unroll
        for (int nt = 0; nt < 8; nt++)
            #pragma unroll
            for (int r = 0; r < 4; r++) s[nt][r] = 0.f;

        const uint32_t kB = sb + 2u*(OFF_K + (t & 1)*BN*SKh + brow*SKh + bcol);
        #pragma unroll
        for (int kc = 0; kc < 8; kc++) {
            uint32_t a0,a1,a2,a3;
            ldsm4(a0,a1,a2,a3, aQ + 32u*kc);
            #pragma unroll
            for (int np = 0; np < 4; np++) {
                uint32_t b0,b1,b2,b3;
                ldsm4(b0,b1,b2,b3, kB + 2u*(np*16*SKh + kc*16));
                mma16(s[2*np],   a0,a1,a2,a3, b0,b1);
                mma16(s[2*np+1], a0,a1,a2,a3, b2,b3);
            }
        }

        // ---- online softmax (ex2); P packed into A-fragment registers ----
        float mt0 = -CUDART_INF_F, mt1 = -CUDART_INF_F;
        #pragma unroll
        for (int nt = 0; nt < 8; nt++) {
            mt0 = fmaxf(mt0, fmaxf(s[nt][0], s[nt][1]));
            mt1 = fmaxf(mt1, fmaxf(s[nt][2], s[nt][3]));
        }
        #pragma unroll
        for (int off = 1; off < 4; off <<= 1) {
            mt0 = fmaxf(mt0, __shfl_xor_sync(0xffffffffu, mt0, off));
            mt1 = fmaxf(mt1, __shfl_xor_sync(0xffffffffu, mt1, off));
        }
        float mn0 = fmaxf(m0, mt0), mn1 = fmaxf(m1, mt1);
        float cor0 = ex2f(m0 - mn0), cor1 = ex2f(m1 - mn1);
        float rs0 = 0.f, rs1 = 0.f;
        uint32_t pa0[8], pa1[8];
        #pragma unroll
        for (int nt = 0; nt < 8; nt++) {
            float p00 = ex2f(s[nt][0] - mn0);
            float p01 = ex2f(s[nt][1] - mn0);
            float p10 = ex2f(s[nt][2] - mn1);
            float p11 = ex2f(s[nt][3] - mn1);
            rs0 += p00 + p01; rs1 += p10 + p11;
            pa0[nt] = h2u(__floats2half2_rn(p00, p01));
            pa1[nt] = h2u(__floats2half2_rn(p10, p11));
        }
        #pragma unroll
        for (int off = 1; off < 4; off <<= 1) {
            rs0 += __shfl_xor_sync(0xffffffffu, rs0, off);
            rs1 += __shfl_xor_sync(0xffffffffu, rs1, off);
        }
        l0 = l0 * cor0 + rs0; m0 = mn0;
        l1 = l1 * cor1 + rs1; m1 = mn1;

        // skip rescale when no row's max changed (cor == 1.0 exactly)
        bool need = (cor0 != 1.f) | (cor1 != 1.f);
        if (__any_sync(0xffffffffu, need)) {
            #pragma unroll
            for (int ct = 0; ct < 16; ct++) {
                o[ct][0] *= cor0; o[ct][1] *= cor0;
                o[ct][2] *= cor1; o[ct][3] *= cor1;
            }
        }

        // ---- O += P V  (A from registers) ----
        const uint32_t vB = sb + 2u*(OFF_V + (t & 1)*C_*SVh + brow*SVh + bcol);
        #pragma unroll
        for (int kc = 0; kc < 4; kc++) {
            uint32_t a0 = pa0[2*kc],   a1 = pa1[2*kc];
            uint32_t a2 = pa0[2*kc+1], a3 = pa1[2*kc+1];
            #pragma unroll
            for (int np = 0; np < 8; np++) {
                uint32_t b0,b1,b2,b3;
                ldsm4(b0,b1,b2,b3, vB + 2u*(np*16*SVh + kc*16));
                mma16(o[2*np],   a0,a1,a2,a3, b0,b1);
                mma16(o[2*np+1], a0,a1,a2,a3, b2,b3);
            }
        }
    }

    // ---- epilogue: out = gamma * O/l + x * se ----
    const float gam = gamma[0];
    const float inv0 = 1.f / l0, inv1 = 1.f / l1;
    const int ir0 = i0 + warp*16 + quad, ir1 = ir0 + 8;
    #pragma unroll
    for (int ct = 0; ct < 16; ct++) {
        int c0 = ct*8 + qt*2;
        float se0 = se_sh[c0], se1 = se_sh[c0 + 1];
        size_t base0 = bcn + (size_t)c0 * N_;
        size_t base1 = base0 + N_;
        out[base0 + ir0] = gam * o[ct][0] * inv0 + x[base0 + ir0] * se0;
        out[base1 + ir0] = gam * o[ct][1] * inv0 + x[base1 + ir0] * se1;
        out[base0 + ir1] = gam * o[ct][2] * inv1 + x[base0 + ir1] * se0;
        out[base1 + ir1] = gam * o[ct][3] * inv1 + x[base1 + ir1] * se1;
    }
}

// ---------------------------------------------------------------------------
extern "C" void kernel_launch(void* const* d_in, const int* in_sizes, int n_in,
                              void* d_out, int out_size)
{
    const float* x     = (const float*)d_in[0];
    const float* Wq    = (const float*)d_in[1];
    const float* bq    = (const float*)d_in[2];
    const float* Wk    = (const float*)d_in[3];
    const float* bk    = (const float*)d_in[4];
    const float* Wv    = (const float*)d_in[5];
    const float* bv    = (const float*)d_in[6];
    const float* se_w1 = (const float*)d_in[7];
    const float* se_w2 = (const float*)d_in[8];
    const float* gamma = (const float*)d_in[9];
    float* out = (float*)d_out;

    static int smem_set = 0;
    if (!smem_set) {
        cudaFuncSetAttribute(attn_kernel,
                             cudaFuncAttributeMaxDynamicSharedMemorySize,
                             SMEM_HALFS * (int)sizeof(__half));
        cudaFuncSetAttribute(qkv_mma_kernel,
                             cudaFuncAttributeMaxDynamicSharedMemorySize,
                             QKV_SMEM_HALFS * (int)sizeof(__half));
        smem_set = 1;
    }

    prep_kernel<<<(W2_TOTAL + 255)/256, 256>>>(Wq, Wk, Wv);
    qkv_mma_kernel<<<dim3(N_/128, B_), 256, QKV_SMEM_HALFS * sizeof(__half)>>>(x, bq, bk, bv);
    attn_kernel<<<dim3(N_/BM, B_), 128, SMEM_HALFS * sizeof(__half)>>>(x, gamma, se_w1, se_w2, out);
}

// round 10
// speedup vs baseline: 1.9533x; 1.0114x over previous
#include <cuda_runtime.h>
#include <cuda_fp16.h>
#include <math_constants.h>
#include <cstdint>

#define B_ 8
#define C_ 128
#define N_ 2304
#define BM 64
#define BN 64
#define NTILE 18
#define LOG2E 1.4426950408889634f

// ---------------- attention smem strides (halfs) ----------------
#define SQh 136
#define SKh 136
#define SVh 72
#define OFF_Q 0
#define OFF_K (BM*SQh)                    // 8704
#define OFF_V (OFF_K + 2*BN*SKh)          // 26112
#define SMEM_HALFS (OFF_V + 3*C_*SVh)     // 53760 halfs = 107520 B (V triple-buffered)

// ---------------- qkv smem strides (halfs) ----------------
#define SX 136
#define SW 136
#define ST 136
#define QOFF_X  0
#define QOFF_W0 (C_*SX)
#define QOFF_W1 (QOFF_W0 + C_*SW)
#define QOFF_T  (QOFF_W1 + C_*SW)
#define QKV_SMEM_HALFS (QOFF_T + C_*ST)

__device__ __half g_qh[B_*N_*C_];   // [b][n][c]  (q pre-scaled by log2e)
__device__ __half g_kh[B_*N_*C_];   // [b][n][c]
__device__ __half g_vh[B_*C_*N_];   // [b][c][n]
__device__ __half g_wh[3*C_*C_];    // [which][o][c]
__device__ float  g_ypart[B_*NTILE*C_];

// ---------------------------------------------------------------------------
__device__ __forceinline__ void cpa16(uint32_t s, const void* g){
    asm volatile("cp.async.cg.shared.global [%0], [%1], 16;" :: "r"(s), "l"(g));
}
__device__ __forceinline__ void cp_commit(){ asm volatile("cp.async.commit_group;"); }
__device__ __forceinline__ void cp_wait1(){ asm volatile("cp.async.wait_group 1;"); }
__device__ __forceinline__ void cp_wait0(){ asm volatile("cp.async.wait_group 0;"); }

__device__ __forceinline__ void ldsm4(uint32_t& r0,uint32_t& r1,uint32_t& r2,uint32_t& r3,
                                      uint32_t a){
    asm volatile("ldmatrix.sync.aligned.m8n8.x4.shared.b16 {%0,%1,%2,%3}, [%4];"
        : "=r"(r0),"=r"(r1),"=r"(r2),"=r"(r3) : "r"(a));
}
__device__ __forceinline__ void ldsm4t(uint32_t& r0,uint32_t& r1,uint32_t& r2,uint32_t& r3,
                                       uint32_t a){
    asm volatile("ldmatrix.sync.aligned.m8n8.x4.trans.shared.b16 {%0,%1,%2,%3}, [%4];"
        : "=r"(r0),"=r"(r1),"=r"(r2),"=r"(r3) : "r"(a));
}
__device__ __forceinline__ void stsm4t(uint32_t a, uint32_t r0,uint32_t r1,uint32_t r2,uint32_t r3){
    asm volatile("stmatrix.sync.aligned.m8n8.x4.trans.shared.b16 [%0], {%1,%2,%3,%4};"
        :: "r"(a), "r"(r0), "r"(r1), "r"(r2), "r"(r3));
}
__device__ __forceinline__ void sts32(uint32_t a, uint32_t v){
    asm volatile("st.shared.b32 [%0], %1;" :: "r"(a), "r"(v));
}
__device__ __forceinline__ void mma16(float* d, uint32_t a0,uint32_t a1,uint32_t a2,uint32_t a3,
                                      uint32_t b0,uint32_t b1){
    asm volatile(
      "mma.sync.aligned.m16n8k16.row.col.f32.f16.f16.f32 "
      "{%0,%1,%2,%3}, {%4,%5,%6,%7}, {%8,%9}, {%0,%1,%2,%3};"
      : "+f"(d[0]), "+f"(d[1]), "+f"(d[2]), "+f"(d[3])
      : "r"(a0), "r"(a1), "r"(a2), "r"(a3), "r"(b0), "r"(b1));
}
__device__ __forceinline__ uint32_t h2u(__half2 h){ return *reinterpret_cast<uint32_t*>(&h); }
__device__ __forceinline__ float ex2f(float x){
    float y; asm("ex2.approx.f32 %0, %1;" : "=f"(y) : "f"(x)); return y;
}

// S-phase: s = Q * K^T for one 64x64 tile (per-warp 16x64)
__device__ __forceinline__ void s_phase(float s[8][4], uint32_t aQ, uint32_t kB){
    #pragma unroll
    for (int nt = 0; nt < 8; nt++)
        #pragma unroll
        for (int r = 0; r < 4; r++) s[nt][r] = 0.f;
    #pragma unroll
    for (int kc = 0; kc < 8; kc++) {
        uint32_t a0,a1,a2,a3;
        ldsm4(a0,a1,a2,a3, aQ + 32u*kc);
        #pragma unroll
        for (int np = 0; np < 4; np++) {
            uint32_t b0,b1,b2,b3;
            ldsm4(b0,b1,b2,b3, kB + 2u*(np*16*SKh + kc*16));
            mma16(s[2*np],   a0,a1,a2,a3, b0,b1);
            mma16(s[2*np+1], a0,a1,a2,a3, b2,b3);
        }
    }
}

// ---------------------------------------------------------------------------
// prep: fp32 -> fp16 for the 3 weight matrices
// ---------------------------------------------------------------------------
#define W2_TOTAL (3*C_*C_/2)
__global__ __launch_bounds__(256) void prep_kernel(
    const float* __restrict__ Wq,
    const float* __restrict__ Wk,
    const float* __restrict__ Wv)
{
    int idx = blockIdx.x * 256 + threadIdx.x;
    if (idx < W2_TOTAL) {
        int which = idx / (C_*C_/2);
        int r = idx - which * (C_*C_/2);
        const float* Wm = (which == 0) ? Wq : (which == 1) ? Wk : Wv;
        float2 v = ((const float2*)Wm)[r];
        ((__half2*)g_wh)[idx] = __floats2half2_rn(v.x, v.y);
    }
}

// ---------------------------------------------------------------------------
// QKV via fp16 tensor cores (unchanged from R9)
// ---------------------------------------------------------------------------
__global__ void __launch_bounds__(256, 1) qkv_mma_kernel(
    const float* __restrict__ x,
    const float* __restrict__ bq,
    const float* __restrict__ bk,
    const float* __restrict__ bv)
{
    extern __shared__ __half smh[];
    uint32_t sb = (uint32_t)__cvta_generic_to_shared(smh);

    const int tid  = threadIdx.x;
    const int b    = blockIdx.y;
    const int n0   = blockIdx.x * 128;
    const int warp = tid >> 5, lane = tid & 31;
    const int quad = lane >> 2, qt = lane & 3;

    const float* xb = x + (size_t)b * C_ * N_;

    #pragma unroll
    for (int c2 = 0; c2 < 8; c2++) {
        int ch = tid + c2*256;
        int o = ch >> 4, cb = ch & 15;
        cpa16(sb + 2u*(QOFF_W0 + o*SW + cb*8), g_wh + o*C_ + cb*8);
    }
    cp_commit();

    #pragma unroll
    for (int c2 = 0; c2 < 8; c2++) {
        int ch = tid + c2*256;
        int c = ch >> 4, nb = ch & 15;
        const float* src = xb + (size_t)c*N_ + n0 + nb*8;
        float4 v0 = *(const float4*)src;
        float4 v1 = *(const float4*)(src + 4);
        uint4 hv;
        hv.x = h2u(__floats2half2_rn(v0.x, v0.y));
        hv.y = h2u(__floats2half2_rn(v0.z, v0.w));
        hv.z = h2u(__floats2half2_rn(v1.x, v1.y));
        hv.w = h2u(__floats2half2_rn(v1.z, v1.w));
        *(uint4*)&smh[QOFF_X + c*SX + nb*8] = hv;
    }
    cp_wait0();
    __syncthreads();

    #pragma unroll
    for (int c2 = 0; c2 < 8; c2++) {
        int ch = tid + c2*256;
        int o = ch >> 4, cb = ch & 15;
        cpa16(sb + 2u*(QOFF_W1 + o*SW + cb*8), g_wh + C_*C_ + o*C_ + cb*8);
    }
    cp_commit();

    if (tid < C_) {
        const uint4* row = (const uint4*)&smh[QOFF_X + tid*SX];
        float s = 0.f;
        #pragma unroll
        for (int u = 0; u < 16; u++) {
            uint4 v = row[u];
            float2 f0 = __half22float2(*(__half2*)&v.x);
            float2 f1 = __half22float2(*(__half2*)&v.y);
            float2 f2 = __half22float2(*(__half2*)&v.z);
            float2 f3 = __half22float2(*(__half2*)&v.w);
            s += (f0.x + f0.y) + (f1.x + f1.y) + (f2.x + f2.y) + (f3.x + f3.y);
        }
        g_ypart[((size_t)b*NTILE + blockIdx.x)*C_ + tid] = s;
    }

    const int r16 = lane & 15;
    const int hi8 = (lane >> 4) * 8;
    const uint32_t bX = sb + 2u*(QOFF_X + r16*SX + hi8);
    const int smm = lane >> 3, smr = lane & 7;
    const uint32_t stb = sb + 2u*(QOFF_T + ((smm>>1)*8 + smr)*ST + warp*16 + (smm&1)*8);
    const uint32_t tst0 = sb + 2u*(QOFF_T + (warp*16 + quad)*ST + qt*2);
    const uint32_t tst1 = tst0 + 2u*8*ST;

    const int o_r0 = warp*16 + quad, o_r1 = o_r0 + 8;

    #pragma unroll
    for (int which = 0; which < 3; which++) {
        const uint32_t wbuf = sb + 2u*((which & 1) ? QOFF_W1 : QOFF_W0);
        const uint32_t aW = wbuf + 2u*((warp*16 + r16)*SW + hi8);

        float acc[16][4];
        #pragma unroll
        for (int nt = 0; nt < 16; nt++)
            #pragma unroll
            for (int r = 0; r < 4; r++) acc[nt][r] = 0.f;

        #pragma unroll
        for (int kc = 0; kc < 8; kc++) {
            uint32_t a0,a1,a2,a3;
            ldsm4(a0,a1,a2,a3, aW + 32u*kc);
            #pragma unroll
            for (int nt16 = 0; nt16 < 8; nt16++) {
                uint32_t b0,b1,b2,b3;
                ldsm4t(b0,b1,b2,b3, bX + 2u*(kc*16*SX + nt16*16));
                mma16(acc[2*nt16],   a0,a1,a2,a3, b0,b1);
                mma16(acc[2*nt16+1], a0,a1,a2,a3, b2,b3);
            }
        }

        const float* bias = (which == 0) ? bq : (which == 1) ? bk : bv;
        const float sc = (which == 0) ? LOG2E : 1.0f;
        float b0f = bias[o_r0], b1f = bias[o_r1];

        if (which < 2) {
            #pragma unroll
            for (int nt16 = 0; nt16 < 8; nt16++) {
                uint32_t r0 = h2u(__floats2half2_rn((acc[2*nt16][0]+b0f)*sc,   (acc[2*nt16][1]+b0f)*sc));
                uint32_t r1 = h2u(__floats2half2_rn((acc[2*nt16][2]+b1f)*sc,   (acc[2*nt16][3]+b1f)*sc));
                uint32_t r2 = h2u(__floats2half2_rn((acc[2*nt16+1][0]+b0f)*sc, (acc[2*nt16+1][1]+b0f)*sc));
                uint32_t r3 = h2u(__floats2half2_rn((acc[2*nt16+1][2]+b1f)*sc, (acc[2*nt16+1][3]+b1f)*sc));
                stsm4t(stb + 2u*(nt16*16*ST), r0, r1, r2, r3);
            }
            __syncthreads();
            if (which == 0) {
                #pragma unroll
                for (int c2 = 0; c2 < 8; c2++) {
                    int ch = tid + c2*256;
                    int o = ch >> 4, cb = ch & 15;
                    cpa16(sb + 2u*(QOFF_W0 + o*SW + cb*8), g_wh + 2*C_*C_ + o*C_ + cb*8);
                }
                cp_commit();
            }
            __half* dsth = (which == 0) ? g_qh : g_kh;
            #pragma unroll
            for (int c2 = 0; c2 < 8; c2++) {
                int ch = tid + c2*256;
                int n = ch >> 4, ob = ch & 15;
                uint4 v = *(uint4*)&smh[QOFF_T + n*ST + ob*8];
                *(uint4*)(dsth + ((size_t)b*N_ + n0 + n)*C_ + ob*8) = v;
            }
            cp_wait0();
            __syncthreads();
        } else {
            #pragma unroll
            for (int nt = 0; nt < 16; nt++) {
                sts32(tst0 + 16u*nt, h2u(__floats2half2_rn(acc[nt][0] + b0f, acc[nt][1] + b0f)));
                sts32(tst1 + 16u*nt, h2u(__floats2half2_rn(acc[nt][2] + b1f, acc[nt][3] + b1f)));
            }
            __syncthreads();
            #pragma unroll
            for (int c2 = 0; c2 < 8; c2++) {
                int ch = tid + c2*256;
                int o = ch >> 4, nb = ch & 15;
                uint4 v = *(uint4*)&smh[QOFF_T + o*ST + nb*8];
                *(uint4*)(g_vh + ((size_t)b*C_ + o)*N_ + n0 + nb*8) = v;
            }
        }
    }
}

// ---------------------------------------------------------------------------
// Flash attention: software-pipelined S(t+1) between softmax(t) and PV(t).
// V triple-buffered, K double-buffered, deferred l-reduction.
// grid (N/64, B), block 128, 2 CTAs/SM.
// ---------------------------------------------------------------------------
__global__ void __launch_bounds__(128, 2) attn_kernel(
    const float* __restrict__ x,
    const float* __restrict__ gamma,
    const float* __restrict__ w1,
    const float* __restrict__ w2,
    float* __restrict__ out)
{
    extern __shared__ __half smh[];
    uint32_t sb = (uint32_t)__cvta_generic_to_shared(smh);
    __shared__ float ym[C_];
    __shared__ float y1_sh[8];
    __shared__ float se_sh[C_];

    const int tid  = threadIdx.x;
    const int b    = blockIdx.y;
    const int i0   = blockIdx.x * BM;
    const int warp = tid >> 5, lane = tid & 31;
    const int quad = lane >> 2, qt = lane & 3;

    const size_t bcn = (size_t)b * C_ * N_;
    const __half* qb = g_qh + (size_t)b * N_ * C_;
    const __half* kb = g_kh + (size_t)b * N_ * C_;
    const __half* vb = g_vh + (size_t)b * C_ * N_;

    // ---- prologue: G0 = (Q, K0, V0); G1 = (K1, V1) ----
    #pragma unroll
    for (int c2 = 0; c2 < 8; c2++) {
        int ch = tid + c2*128;
        int i = ch >> 4, cb = ch & 15;
        cpa16(sb + 2u*(OFF_Q + i*SQh + cb*8), qb + (size_t)(i0 + i)*C_ + cb*8);
    }
    #pragma unroll
    for (int c2 = 0; c2 < 8; c2++) {
        int ch = tid + c2*128;
        int j = ch >> 4, cb = ch & 15;
        cpa16(sb + 2u*(OFF_K + j*SKh + cb*8), kb + (size_t)j*C_ + cb*8);
    }
    #pragma unroll
    for (int c2 = 0; c2 < 8; c2++) {
        int ch = tid + c2*128;
        int c = ch >> 3, cb = ch & 7;
        cpa16(sb + 2u*(OFF_V + c*SVh + cb*8), vb + (size_t)c*N_ + cb*8);
    }
    cp_commit();
    #pragma unroll
    for (int c2 = 0; c2 < 8; c2++) {
        int ch = tid + c2*128;
        int j = ch >> 4, cb = ch & 15;
        cpa16(sb + 2u*(OFF_K + BN*SKh + j*SKh + cb*8), kb + (size_t)(BN + j)*C_ + cb*8);
    }
    #pragma unroll
    for (int c2 = 0; c2 < 8; c2++) {
        int ch = tid + c2*128;
        int c = ch >> 3, cb = ch & 7;
        cpa16(sb + 2u*(OFF_V + C_*SVh + c*SVh + cb*8), vb + (size_t)c*N_ + BN + cb*8);
    }
    cp_commit();

    // ---- SE MLP (overlapped with prologue cp.async) ----
    {
        float acc = 0.f;
        #pragma unroll
        for (int tt = 0; tt < NTILE; tt++)
            acc += g_ypart[((size_t)b*NTILE + tt)*C_ + tid];
        ym[tid] = acc * (1.f / (float)N_);
    }
    __syncthreads();
    {
        int h = tid >> 4, cl = tid & 15;
        float p = 0.f;
        #pragma unroll
        for (int u = 0; u < 8; u++) {
            int c = cl + u*16;
            p += w1[h*C_ + c] * ym[c];
        }
        #pragma unroll
        for (int off = 1; off < 16; off <<= 1)
            p += __shfl_xor_sync(0xffffffffu, p, off);
        if (cl == 0) y1_sh[h] = fmaxf(p, 0.f);
    }
    __syncthreads();
    {
        float a = 0.f;
        #pragma unroll
        for (int r = 0; r < 8; r++) a += w2[tid*8 + r] * y1_sh[r];
        se_sh[tid] = 1.f / (1.f + ex2f(-a * LOG2E));
    }

    cp_wait1();          // K0, V0 resident
    __syncthreads();

    float o[16][4];
    #pragma unroll
    for (int ct = 0; ct < 16; ct++)
        #pragma unroll
        for (int r = 0; r < 4; r++) o[ct][r] = 0.f;
    float m0 = -CUDART_INF_F, m1 = -CUDART_INF_F, l0 = 0.f, l1 = 0.f;

    const int r16  = lane & 15;
    const int ahi  = (lane >> 4) * 8;
    const int brow = (lane & 7) + ((lane >> 4) & 1) * 8;
    const int bcol = ((lane >> 3) & 1) * 8;

    const uint32_t aQ = sb + 2u*(OFF_Q + (warp*16 + r16)*SQh + ahi);

    // ---- S(0) ----
    float s[8][4];
    s_phase(s, aQ, sb + 2u*(OFF_K + brow*SKh + bcol));

    int vcur = 0, vnext2 = 2;   // V(t) buffer, V(t+2) buffer
    for (int t = 0; t < 36; t++) {
        // ---- 1. softmax(t): s -> pa; deferred l (no shuffle) ----
        float mt0 = -CUDART_INF_F, mt1 = -CUDART_INF_F;
        #pragma unroll
        for (int nt = 0; nt < 8; nt++) {
            mt0 = fmaxf(mt0, fmaxf(s[nt][0], s[nt][1]));
            mt1 = fmaxf(mt1, fmaxf(s[nt][2], s[nt][3]));
        }
        #pragma unroll
        for (int off = 1; off < 4; off <<= 1) {
            mt0 = fmaxf(mt0, __shfl_xor_sync(0xffffffffu, mt0, off));
            mt1 = fmaxf(mt1, __shfl_xor_sync(0xffffffffu, mt1, off));
        }
        float mn0 = fmaxf(m0, mt0), mn1 = fmaxf(m1, mt1);
        float cor0 = ex2f(m0 - mn0), cor1 = ex2f(m1 - mn1);
        float rs0 = 0.f, rs1 = 0.f;
        uint32_t pa0[8], pa1[8];
        #pragma unroll
        for (int nt = 0; nt < 8; nt++) {
            float p00 = ex2f(s[nt][0] - mn0);
            float p01 = ex2f(s[nt][1] - mn0);
            float p10 = ex2f(s[nt][2] - mn1);
            float p11 = ex2f(s[nt][3] - mn1);
            rs0 += p00 + p01; rs1 += p10 + p11;
            pa0[nt] = h2u(__floats2half2_rn(p00, p01));
            pa1[nt] = h2u(__floats2half2_rn(p10, p11));
        }
        l0 = l0 * cor0 + rs0; m0 = mn0;   // per-thread partial
        l1 = l1 * cor1 + rs1; m1 = mn1;

        bool need = (cor0 != 1.f) | (cor1 != 1.f);
        if (__any_sync(0xffffffffu, need)) {
            #pragma unroll
            for (int ct = 0; ct < 16; ct++) {
                o[ct][0] *= cor0; o[ct][1] *= cor0;
                o[ct][2] *= cor1; o[ct][3] *= cor1;
            }
        }

        // ---- 2. K(t+1)/V(t+1) resident; all warps past reads of overwritten bufs ----
        cp_wait0();
        __syncthreads();

        // ---- 3. stage K(t+2), V(t+2) ----
        if (t <= 33) {
            const int jn = (t + 2) * BN;
            const uint32_t kdst = sb + 2u*(OFF_K + (t & 1)*BN*SKh);
            const uint32_t vdst = sb + 2u*(OFF_V + vnext2*C_*SVh);
            #pragma unroll
            for (int c2 = 0; c2 < 8; c2++) {
                int ch = tid + c2*128;
                int j = ch >> 4, cb = ch & 15;
                cpa16(kdst + 2u*(j*SKh + cb*8), kb + (size_t)(jn + j)*C_ + cb*8);
            }
            #pragma unroll
            for (int c2 = 0; c2 < 8; c2++) {
                int ch = tid + c2*128;
                int c = ch >> 3, cb = ch & 7;
                cpa16(vdst + 2u*(c*SVh + cb*8), vb + (size_t)c*N_ + jn + cb*8);
            }
            cp_commit();
        }

        // ---- 4. S(t+1): s regs reused; independent of pa -> hides softmax latency ----
        if (t < 35)
            s_phase(s, aQ, sb + 2u*(OFF_K + ((t+1)&1)*BN*SKh + brow*SKh + bcol));

        // ---- 5. PV(t): o += pa * V(t) ----
        const uint32_t vB = sb + 2u*(OFF_V + vcur*C_*SVh + brow*SVh + bcol);
        #pragma unroll
        for (int kc = 0; kc < 4; kc++) {
            uint32_t a0 = pa0[2*kc],   a1 = pa1[2*kc];
            uint32_t a2 = pa0[2*kc+1], a3 = pa1[2*kc+1];
            #pragma unroll
            for (int np = 0; np < 8; np++) {
                uint32_t b0,b1,b2,b3;
                ldsm4(b0,b1,b2,b3, vB + 2u*(np*16*SVh + kc*16));
                mma16(o[2*np],   a0,a1,a2,a3, b0,b1);
                mma16(o[2*np+1], a0,a1,a2,a3, b2,b3);
            }
        }

        vcur   = (vcur   == 2) ? 0 : vcur + 1;
        vnext2 = (vnext2 == 2) ? 0 : vnext2 + 1;
    }

    // ---- epilogue: reduce l partials across quad, then combine ----
    #pragma unroll
    for (int off = 1; off < 4; off <<= 1) {
        l0 += __shfl_xor_sync(0xffffffffu, l0, off);
        l1 += __shfl_xor_sync(0xffffffffu, l1, off);
    }
    const float gam = gamma[0];
    const float inv0 = 1.f / l0, inv1 = 1.f / l1;
    const int ir0 = i0 + warp*16 + quad, ir1 = ir0 + 8;
    #pragma unroll
    for (int ct = 0; ct < 16; ct++) {
        int c0 = ct*8 + qt*2;
        float se0 = se_sh[c0], se1 = se_sh[c0 + 1];
        size_t base0 = bcn + (size_t)c0 * N_;
        size_t base1 = base0 + N_;
        out[base0 + ir0] = gam * o[ct][0] * inv0 + x[base0 + ir0] * se0;
        out[base1 + ir0] = gam * o[ct][1] * inv0 + x[base1 + ir0] * se1;
        out[base0 + ir1] = gam * o[ct][2] * inv1 + x[base0 + ir1] * se0;
        out[base1 + ir1] = gam * o[ct][3] * inv1 + x[base1 + ir1] * se1;
    }
}

// ---------------------------------------------------------------------------
extern "C" void kernel_launch(void* const* d_in, const int* in_sizes, int n_in,
                              void* d_out, int out_size)
{
    const float* x     = (const float*)d_in[0];
    const float* Wq    = (const float*)d_in[1];
    const float* bq    = (const float*)d_in[2];
    const float* Wk    = (const float*)d_in[3];
    const float* bk    = (const float*)d_in[4];
    const float* Wv    = (const float*)d_in[5];
    const float* bv    = (const float*)d_in[6];
    const float* se_w1 = (const float*)d_in[7];
    const float* se_w2 = (const float*)d_in[8];
    const float* gamma = (const float*)d_in[9];
    float* out = (float*)d_out;

    static int smem_set = 0;
    if (!smem_set) {
        cudaFuncSetAttribute(attn_kernel,
                             cudaFuncAttributeMaxDynamicSharedMemorySize,
                             SMEM_HALFS * (int)sizeof(__half));
        cudaFuncSetAttribute(qkv_mma_kernel,
                             cudaFuncAttributeMaxDynamicSharedMemorySize,
                             QKV_SMEM_HALFS * (int)sizeof(__half));
        smem_set = 1;
    }

    prep_kernel<<<(W2_TOTAL + 255)/256, 256>>>(Wq, Wk, Wv);
    qkv_mma_kernel<<<dim3(N_/128, B_), 256, QKV_SMEM_HALFS * sizeof(__half)>>>(x, bq, bk, bv);
    attn_kernel<<<dim3(N_/BM, B_), 128, SMEM_HALFS * sizeof(__half)>>>(x, gamma, se_w1, se_w2, out);
}

// round 12
// speedup vs baseline: 1.9732x; 1.0102x over previous
#include <cuda_runtime.h>
#include <cuda_fp16.h>
#include <math_constants.h>
#include <cstdint>

#define B_ 8
#define C_ 128
#define N_ 2304
#define BM 64
#define BN 64
#define NTILE 18
#define LOG2E 1.4426950408889634f

// ---------------- attention smem strides (halfs) ----------------
#define SQh 136
#define SKh 136
#define SVh 72
#define OFF_Q 0
#define OFF_K (BM*SQh)                    // 8704
#define OFF_V (OFF_K + 2*BN*SKh)          // 26112
#define SMEM_HALFS (OFF_V + 3*C_*SVh)     // 53760 halfs = 107520 B

// ---------------- qkv smem strides (halfs) ----------------
#define SX 136
#define SW 136
#define ST 136
#define QOFF_X  0
#define QOFF_W0 (C_*SX)
#define QOFF_W1 (QOFF_W0 + C_*SW)
#define QOFF_T  (QOFF_W1 + C_*SW)
#define QKV_SMEM_HALFS (QOFF_T + C_*ST)

__device__ __half g_qh[B_*N_*C_];   // [b][n][c]  (q pre-scaled by log2e)
__device__ __half g_kh[B_*N_*C_];   // [b][n][c]
__device__ __half g_vh[B_*C_*N_];   // [b][c][n]
__device__ __half g_wh[3*C_*C_];    // [which][o][c]
__device__ float  g_ypart[B_*NTILE*C_];

// ---------------------------------------------------------------------------
__device__ __forceinline__ void cpa16(uint32_t s, const void* g){
    asm volatile("cp.async.cg.shared.global [%0], [%1], 16;" :: "r"(s), "l"(g));
}
__device__ __forceinline__ void cp_commit(){ asm volatile("cp.async.commit_group;"); }
__device__ __forceinline__ void cp_wait1(){ asm volatile("cp.async.wait_group 1;"); }
__device__ __forceinline__ void cp_wait0(){ asm volatile("cp.async.wait_group 0;"); }

__device__ __forceinline__ void ldsm4(uint32_t& r0,uint32_t& r1,uint32_t& r2,uint32_t& r3,
                                      uint32_t a){
    asm volatile("ldmatrix.sync.aligned.m8n8.x4.shared.b16 {%0,%1,%2,%3}, [%4];"
        : "=r"(r0),"=r"(r1),"=r"(r2),"=r"(r3) : "r"(a));
}
__device__ __forceinline__ void ldsm4t(uint32_t& r0,uint32_t& r1,uint32_t& r2,uint32_t& r3,
                                       uint32_t a){
    asm volatile("ldmatrix.sync.aligned.m8n8.x4.trans.shared.b16 {%0,%1,%2,%3}, [%4];"
        : "=r"(r0),"=r"(r1),"=r"(r2),"=r"(r3) : "r"(a));
}
__device__ __forceinline__ void stsm4t(uint32_t a, uint32_t r0,uint32_t r1,uint32_t r2,uint32_t r3){
    asm volatile("stmatrix.sync.aligned.m8n8.x4.trans.shared.b16 [%0], {%1,%2,%3,%4};"
        :: "r"(a), "r"(r0), "r"(r1), "r"(r2), "r"(r3));
}
__device__ __forceinline__ void sts32(uint32_t a, uint32_t v){
    asm volatile("st.shared.b32 [%0], %1;" :: "r"(a), "r"(v));
}
__device__ __forceinline__ void mma16(float* d, uint32_t a0,uint32_t a1,uint32_t a2,uint32_t a3,
                                      uint32_t b0,uint32_t b1){
    asm volatile(
      "mma.sync.aligned.m16n8k16.row.col.f32.f16.f16.f32 "
      "{%0,%1,%2,%3}, {%4,%5,%6,%7}, {%8,%9}, {%0,%1,%2,%3};"
      : "+f"(d[0]), "+f"(d[1]), "+f"(d[2]), "+f"(d[3])
      : "r"(a0), "r"(a1), "r"(a2), "r"(a3), "r"(b0), "r"(b1));
}
__device__ __forceinline__ uint32_t h2u(__half2 h){ return *reinterpret_cast<uint32_t*>(&h); }
__device__ __forceinline__ float ex2f(float x){
    float y; asm("ex2.approx.f32 %0, %1;" : "=f"(y) : "f"(x)); return y;
}
// two exponentials per MUFU op
__device__ __forceinline__ uint32_t ex2_h2(uint32_t u){
    uint32_t r; asm("ex2.approx.f16x2 %0, %1;" : "=r"(r) : "r"(u)); return r;
}

// S-phase: s = Q * K^T for one 64x64 tile (per-warp 16x64)
__device__ __forceinline__ void s_phase(float s[8][4], uint32_t aQ, uint32_t kB){
    #pragma unroll
    for (int nt = 0; nt < 8; nt++)
        #pragma unroll
        for (int r = 0; r < 4; r++) s[nt][r] = 0.f;
    #pragma unroll
    for (int kc = 0; kc < 8; kc++) {
        uint32_t a0,a1,a2,a3;
        ldsm4(a0,a1,a2,a3, aQ + 32u*kc);
        #pragma unroll
        for (int np = 0; np < 4; np++) {
            uint32_t b0,b1,b2,b3;
            ldsm4(b0,b1,b2,b3, kB + 2u*(np*16*SKh + kc*16));
            mma16(s[2*np],   a0,a1,a2,a3, b0,b1);
            mma16(s[2*np+1], a0,a1,a2,a3, b2,b3);
        }
    }
}

// ---------------------------------------------------------------------------
// prep: fp32 -> fp16 for the 3 weight matrices
// ---------------------------------------------------------------------------
#define W2_TOTAL (3*C_*C_/2)
__global__ __launch_bounds__(256) void prep_kernel(
    const float* __restrict__ Wq,
    const float* __restrict__ Wk,
    const float* __restrict__ Wv)
{
    int idx = blockIdx.x * 256 + threadIdx.x;
    if (idx < W2_TOTAL) {
        int which = idx / (C_*C_/2);
        int r = idx - which * (C_*C_/2);
        const float* Wm = (which == 0) ? Wq : (which == 1) ? Wk : Wv;
        float2 v = ((const float2*)Wm)[r];
        ((__half2*)g_wh)[idx] = __floats2half2_rn(v.x, v.y);
    }
}

// ---------------------------------------------------------------------------
// QKV via fp16 tensor cores (unchanged)
// ---------------------------------------------------------------------------
__global__ void __launch_bounds__(256, 1) qkv_mma_kernel(
    const float* __restrict__ x,
    const float* __restrict__ bq,
    const float* __restrict__ bk,
    const float* __restrict__ bv)
{
    extern __shared__ __half smh[];
    uint32_t sb = (uint32_t)__cvta_generic_to_shared(smh);

    const int tid  = threadIdx.x;
    const int b    = blockIdx.y;
    const int n0   = blockIdx.x * 128;
    const int warp = tid >> 5, lane = tid & 31;
    const int quad = lane >> 2, qt = lane & 3;

    const float* xb = x + (size_t)b * C_ * N_;

    #pragma unroll
    for (int c2 = 0; c2 < 8; c2++) {
        int ch = tid + c2*256;
        int o = ch >> 4, cb = ch & 15;
        cpa16(sb + 2u*(QOFF_W0 + o*SW + cb*8), g_wh + o*C_ + cb*8);
    }
    cp_commit();

    #pragma unroll
    for (int c2 = 0; c2 < 8; c2++) {
        int ch = tid + c2*256;
        int c = ch >> 4, nb = ch & 15;
        const float* src = xb + (size_t)c*N_ + n0 + nb*8;
        float4 v0 = *(const float4*)src;
        float4 v1 = *(const float4*)(src + 4);
        uint4 hv;
        hv.x = h2u(__floats2half2_rn(v0.x, v0.y));
        hv.y = h2u(__floats2half2_rn(v0.z, v0.w));
        hv.z = h2u(__floats2half2_rn(v1.x, v1.y));
        hv.w = h2u(__floats2half2_rn(v1.z, v1.w));
        *(uint4*)&smh[QOFF_X + c*SX + nb*8] = hv;
    }
    cp_wait0();
    __syncthreads();

    #pragma unroll
    for (int c2 = 0; c2 < 8; c2++) {
        int ch = tid + c2*256;
        int o = ch >> 4, cb = ch & 15;
        cpa16(sb + 2u*(QOFF_W1 + o*SW + cb*8), g_wh + C_*C_ + o*C_ + cb*8);
    }
    cp_commit();

    if (tid < C_) {
        const uint4* row = (const uint4*)&smh[QOFF_X + tid*SX];
        float s = 0.f;
        #pragma unroll
        for (int u = 0; u < 16; u++) {
            uint4 v = row[u];
            float2 f0 = __half22float2(*(__half2*)&v.x);
            float2 f1 = __half22float2(*(__half2*)&v.y);
            float2 f2 = __half22float2(*(__half2*)&v.z);
            float2 f3 = __half22float2(*(__half2*)&v.w);
            s += (f0.x + f0.y) + (f1.x + f1.y) + (f2.x + f2.y) + (f3.x + f3.y);
        }
        g_ypart[((size_t)b*NTILE + blockIdx.x)*C_ + tid] = s;
    }

    const int r16 = lane & 15;
    const int hi8 = (lane >> 4) * 8;
    const uint32_t bX = sb + 2u*(QOFF_X + r16*SX + hi8);
    const int smm = lane >> 3, smr = lane & 7;
    const uint32_t stb = sb + 2u*(QOFF_T + ((smm>>1)*8 + smr)*ST + warp*16 + (smm&1)*8);
    const uint32_t tst0 = sb + 2u*(QOFF_T + (warp*16 + quad)*ST + qt*2);
    const uint32_t tst1 = tst0 + 2u*8*ST;

    const int o_r0 = warp*16 + quad, o_r1 = o_r0 + 8;

    #pragma unroll
    for (int which = 0; which < 3; which++) {
        const uint32_t wbuf = sb + 2u*((which & 1) ? QOFF_W1 : QOFF_W0);
        const uint32_t aW = wbuf + 2u*((warp*16 + r16)*SW + hi8);

        float acc[16][4];
        #pragma unroll
        for (int nt = 0; nt < 16; nt++)
            #pragma unroll
            for (int r = 0; r < 4; r++) acc[nt][r] = 0.f;

        #pragma unroll
        for (int kc = 0; kc < 8; kc++) {
            uint32_t a0,a1,a2,a3;
            ldsm4(a0,a1,a2,a3, aW + 32u*kc);
            #pragma unroll
            for (int nt16 = 0; nt16 < 8; nt16++) {
                uint32_t b0,b1,b2,b3;
                ldsm4t(b0,b1,b2,b3, bX + 2u*(kc*16*SX + nt16*16));
                mma16(acc[2*nt16],   a0,a1,a2,a3, b0,b1);
                mma16(acc[2*nt16+1], a0,a1,a2,a3, b2,b3);
            }
        }

        const float* bias = (which == 0) ? bq : (which == 1) ? bk : bv;
        const float sc = (which == 0) ? LOG2E : 1.0f;
        float b0f = bias[o_r0], b1f = bias[o_r1];

        if (which < 2) {
            #pragma unroll
            for (int nt16 = 0; nt16 < 8; nt16++) {
                uint32_t r0 = h2u(__floats2half2_rn((acc[2*nt16][0]+b0f)*sc,   (acc[2*nt16][1]+b0f)*sc));
                uint32_t r1 = h2u(__floats2half2_rn((acc[2*nt16][2]+b1f)*sc,   (acc[2*nt16][3]+b1f)*sc));
                uint32_t r2 = h2u(__floats2half2_rn((acc[2*nt16+1][0]+b0f)*sc, (acc[2*nt16+1][1]+b0f)*sc));
                uint32_t r3 = h2u(__floats2half2_rn((acc[2*nt16+1][2]+b1f)*sc, (acc[2*nt16+1][3]+b1f)*sc));
                stsm4t(stb + 2u*(nt16*16*ST), r0, r1, r2, r3);
            }
            __syncthreads();
            if (which == 0) {
                #pragma unroll
                for (int c2 = 0; c2 < 8; c2++) {
                    int ch = tid + c2*256;
                    int o = ch >> 4, cb = ch & 15;
                    cpa16(sb + 2u*(QOFF_W0 + o*SW + cb*8), g_wh + 2*C_*C_ + o*C_ + cb*8);
                }
                cp_commit();
            }
            __half* dsth = (which == 0) ? g_qh : g_kh;
            #pragma unroll
            for (int c2 = 0; c2 < 8; c2++) {
                int ch = tid + c2*256;
                int n = ch >> 4, ob = ch & 15;
                uint4 v = *(uint4*)&smh[QOFF_T + n*ST + ob*8];
                *(uint4*)(dsth + ((size_t)b*N_ + n0 + n)*C_ + ob*8) = v;
            }
            cp_wait0();
            __syncthreads();
        } else {
            #pragma unroll
            for (int nt = 0; nt < 16; nt++) {
                sts32(tst0 + 16u*nt, h2u(__floats2half2_rn(acc[nt][0] + b0f, acc[nt][1] + b0f)));
                sts32(tst1 + 16u*nt, h2u(__floats2half2_rn(acc[nt][2] + b1f, acc[nt][3] + b1f)));
            }
            __syncthreads();
            #pragma unroll
            for (int c2 = 0; c2 < 8; c2++) {
                int ch = tid + c2*256;
                int o = ch >> 4, nb = ch & 15;
                uint4 v = *(uint4*)&smh[QOFF_T + o*ST + nb*8];
                *(uint4*)(g_vh + ((size_t)b*C_ + o)*N_ + n0 + nb*8) = v;
            }
        }
    }
}

// ---------------------------------------------------------------------------
// Flash attention: MUFU-halved softmax via ex2.approx.f16x2.
// grid (N/64, B), block 128, 2 CTAs/SM.
// ---------------------------------------------------------------------------
__global__ void __launch_bounds__(128, 2) attn_kernel(
    const float* __restrict__ x,
    const float* __restrict__ gamma,
    const float* __restrict__ w1,
    const float* __restrict__ w2,
    float* __restrict__ out)
{
    extern __shared__ __half smh[];
    uint32_t sb = (uint32_t)__cvta_generic_to_shared(smh);
    __shared__ float ym[C_];
    __shared__ float y1_sh[8];
    __shared__ float se_sh[C_];

    const int tid  = threadIdx.x;
    const int b    = blockIdx.y;
    const int i0   = blockIdx.x * BM;
    const int warp = tid >> 5, lane = tid & 31;
    const int quad = lane >> 2, qt = lane & 3;

    const size_t bcn = (size_t)b * C_ * N_;
    const __half* qb = g_qh + (size_t)b * N_ * C_;
    const __half* kb = g_kh + (size_t)b * N_ * C_;
    const __half* vb = g_vh + (size_t)b * C_ * N_;

    // ---- prologue: G0 = (Q, K0, V0); G1 = (K1, V1) ----
    #pragma unroll
    for (int c2 = 0; c2 < 8; c2++) {
        int ch = tid + c2*128;
        int i = ch >> 4, cb = ch & 15;
        cpa16(sb + 2u*(OFF_Q + i*SQh + cb*8), qb + (size_t)(i0 + i)*C_ + cb*8);
    }
    #pragma unroll
    for (int c2 = 0; c2 < 8; c2++) {
        int ch = tid + c2*128;
        int j = ch >> 4, cb = ch & 15;
        cpa16(sb + 2u*(OFF_K + j*SKh + cb*8), kb + (size_t)j*C_ + cb*8);
    }
    #pragma unroll
    for (int c2 = 0; c2 < 8; c2++) {
        int ch = tid + c2*128;
        int c = ch >> 3, cb = ch & 7;
        cpa16(sb + 2u*(OFF_V + c*SVh + cb*8), vb + (size_t)c*N_ + cb*8);
    }
    cp_commit();
    #pragma unroll
    for (int c2 = 0; c2 < 8; c2++) {
        int ch = tid + c2*128;
        int j = ch >> 4, cb = ch & 15;
        cpa16(sb + 2u*(OFF_K + BN*SKh + j*SKh + cb*8), kb + (size_t)(BN + j)*C_ + cb*8);
    }
    #pragma unroll
    for (int c2 = 0; c2 < 8; c2++) {
        int ch = tid + c2*128;
        int c = ch >> 3, cb = ch & 7;
        cpa16(sb + 2u*(OFF_V + C_*SVh + c*SVh + cb*8), vb + (size_t)c*N_ + BN + cb*8);
    }
    cp_commit();

    // ---- SE MLP (overlapped with prologue cp.async) ----
    {
        float acc = 0.f;
        #pragma unroll
        for (int tt = 0; tt < NTILE; tt++)
            acc += g_ypart[((size_t)b*NTILE + tt)*C_ + tid];
        ym[tid] = acc * (1.f / (float)N_);
    }
    __syncthreads();
    {
        int h = tid >> 4, cl = tid & 15;
        float p = 0.f;
        #pragma unroll
        for (int u = 0; u < 8; u++) {
            int c = cl + u*16;
            p += w1[h*C_ + c] * ym[c];
        }
        #pragma unroll
        for (int off = 1; off < 16; off <<= 1)
            p += __shfl_xor_sync(0xffffffffu, p, off);
        if (cl == 0) y1_sh[h] = fmaxf(p, 0.f);
    }
    __syncthreads();
    {
        float a = 0.f;
        #pragma unroll
        for (int r = 0; r < 8; r++) a += w2[tid*8 + r] * y1_sh[r];
        se_sh[tid] = 1.f / (1.f + ex2f(-a * LOG2E));
    }

    cp_wait1();
    __syncthreads();

    float o[16][4];
    #pragma unroll
    for (int ct = 0; ct < 16; ct++)
        #pragma unroll
        for (int r = 0; r < 4; r++) o[ct][r] = 0.f;
    float m0 = -CUDART_INF_F, m1 = -CUDART_INF_F, l0 = 0.f, l1 = 0.f;

    const int r16  = lane & 15;
    const int ahi  = (lane >> 4) * 8;
    const int brow = (lane & 7) + ((lane >> 4) & 1) * 8;
    const int bcol = ((lane >> 3) & 1) * 8;

    const uint32_t aQ = sb + 2u*(OFF_Q + (warp*16 + r16)*SQh + ahi);

    // ---- S(0) ----
    float s[8][4];
    s_phase(s, aQ, sb + 2u*(OFF_K + brow*SKh + bcol));

    int vcur = 0, vnext2 = 2;
    for (int t = 0; t < 36; t++) {
        // ---- 1. softmax(t): half2 exponentials (1 MUFU per 2 probs) ----
        float mt0 = -CUDART_INF_F, mt1 = -CUDART_INF_F;
        #pragma unroll
        for (int nt = 0; nt < 8; nt++) {
            mt0 = fmaxf(mt0, fmaxf(s[nt][0], s[nt][1]));
            mt1 = fmaxf(mt1, fmaxf(s[nt][2], s[nt][3]));
        }
        #pragma unroll
        for (int off = 1; off < 4; off <<= 1) {
            mt0 = fmaxf(mt0, __shfl_xor_sync(0xffffffffu, mt0, off));
            mt1 = fmaxf(mt1, __shfl_xor_sync(0xffffffffu, mt1, off));
        }
        float mn0 = fmaxf(m0, mt0), mn1 = fmaxf(m1, mt1);
        float cor0 = ex2f(m0 - mn0), cor1 = ex2f(m1 - mn1);
        float rs0 = 0.f, rs1 = 0.f;
        uint32_t pa0[8], pa1[8];
        #pragma unroll
        for (int nt = 0; nt < 8; nt++) {
            pa0[nt] = ex2_h2(h2u(__floats2half2_rn(s[nt][0] - mn0, s[nt][1] - mn0)));
            pa1[nt] = ex2_h2(h2u(__floats2half2_rn(s[nt][2] - mn1, s[nt][3] - mn1)));
            float2 f0 = __half22float2(*(__half2*)&pa0[nt]);
            float2 f1 = __half22float2(*(__half2*)&pa1[nt]);
            rs0 += f0.x + f0.y;
            rs1 += f1.x + f1.y;
        }
        l0 = l0 * cor0 + rs0; m0 = mn0;
        l1 = l1 * cor1 + rs1; m1 = mn1;

        bool need = (cor0 != 1.f) | (cor1 != 1.f);
        if (__any_sync(0xffffffffu, need)) {
            #pragma unroll
            for (int ct = 0; ct < 16; ct++) {
                o[ct][0] *= cor0; o[ct][1] *= cor0;
                o[ct][2] *= cor1; o[ct][3] *= cor1;
            }
        }

        // ---- 2. K(t+1)/V(t+1) resident ----
        cp_wait0();
        __syncthreads();

        // ---- 3. stage K(t+2), V(t+2) ----
        if (t <= 33) {
            const int jn = (t + 2) * BN;
            const uint32_t kdst = sb + 2u*(OFF_K + (t & 1)*BN*SKh);
            const uint32_t vdst = sb + 2u*(OFF_V + vnext2*C_*SVh);
            #pragma unroll
            for (int c2 = 0; c2 < 8; c2++) {
                int ch = tid + c2*128;
                int j = ch >> 4, cb = ch & 15;
                cpa16(kdst + 2u*(j*SKh + cb*8), kb + (size_t)(jn + j)*C_ + cb*8);
            }
            #pragma unroll
            for (int c2 = 0; c2 < 8; c2++) {
                int ch = tid + c2*128;
                int c = ch >> 3, cb = ch & 7;
                cpa16(vdst + 2u*(c*SVh + cb*8), vb + (size_t)c*N_ + jn + cb*8);
            }
            cp_commit();
        }

        // ---- 4. S(t+1) ----
        if (t < 35)
            s_phase(s, aQ, sb + 2u*(OFF_K + ((t+1)&1)*BN*SKh + brow*SKh + bcol));

        // ---- 5. PV(t) ----
        const uint32_t vB = sb + 2u*(OFF_V + vcur*C_*SVh + brow*SVh + bcol);
        #pragma unroll
        for (int kc = 0; kc < 4; kc++) {
            uint32_t a0 = pa0[2*kc],   a1 = pa1[2*kc];
            uint32_t a2 = pa0[2*kc+1], a3 = pa1[2*kc+1];
            #pragma unroll
            for (int np = 0; np < 8; np++) {
                uint32_t b0,b1,b2,b3;
                ldsm4(b0,b1,b2,b3, vB + 2u*(np*16*SVh + kc*16));
                mma16(o[2*np],   a0,a1,a2,a3, b0,b1);
                mma16(o[2*np+1], a0,a1,a2,a3, b2,b3);
            }
        }

        vcur   = (vcur   == 2) ? 0 : vcur + 1;
        vnext2 = (vnext2 == 2) ? 0 : vnext2 + 1;
    }

    // ---- epilogue ----
    #pragma unroll
    for (int off = 1; off < 4; off <<= 1) {
        l0 += __shfl_xor_sync(0xffffffffu, l0, off);
        l1 += __shfl_xor_sync(0xffffffffu, l1, off);
    }
    const float gam = gamma[0];
    const float inv0 = 1.f / l0, inv1 = 1.f / l1;
    const int ir0 = i0 + warp*16 + quad, ir1 = ir0 + 8;
    #pragma unroll
    for (int ct = 0; ct < 16; ct++) {
        int c0 = ct*8 + qt*2;
        float se0 = se_sh[c0], se1 = se_sh[c0 + 1];
        size_t base0 = bcn + (size_t)c0 * N_;
        size_t base1 = base0 + N_;
        out[base0 + ir0] = gam * o[ct][0] * inv0 + x[base0 + ir0] * se0;
        out[base1 + ir0] = gam * o[ct][1] * inv0 + x[base1 + ir0] * se1;
        out[base0 + ir1] = gam * o[ct][2] * inv1 + x[base0 + ir1] * se0;
        out[base1 + ir1] = gam * o[ct][3] * inv1 + x[base1 + ir1] * se1;
    }
}

// ---------------------------------------------------------------------------
extern "C" void kernel_launch(void* const* d_in, const int* in_sizes, int n_in,
                              void* d_out, int out_size)
{
    const float* x     = (const float*)d_in[0];
    const float* Wq    = (const float*)d_in[1];
    const float* bq    = (const float*)d_in[2];
    const float* Wk    = (const float*)d_in[3];
    const float* bk    = (const float*)d_in[4];
    const float* Wv    = (const float*)d_in[5];
    const float* bv    = (const float*)d_in[6];
    const float* se_w1 = (const float*)d_in[7];
    const float* se_w2 = (const float*)d_in[8];
    const float* gamma = (const float*)d_in[9];
    float* out = (float*)d_out;

    static int smem_set = 0;
    if (!smem_set) {
        cudaFuncSetAttribute(attn_kernel,
                             cudaFuncAttributeMaxDynamicSharedMemorySize,
                             SMEM_HALFS * (int)sizeof(__half));
        cudaFuncSetAttribute(qkv_mma_kernel,
                             cudaFuncAttributeMaxDynamicSharedMemorySize,
                             QKV_SMEM_HALFS * (int)sizeof(__half));
        smem_set = 1;
    }

    prep_kernel<<<(W2_TOTAL + 255)/256, 256>>>(Wq, Wk, Wv);
    qkv_mma_kernel<<<dim3(N_/128, B_), 256, QKV_SMEM_HALFS * sizeof(__half)>>>(x, bq, bk, bv);
    attn_kernel<<<dim3(N_/BM, B_), 128, SMEM_HALFS * sizeof(__half)>>>(x, gamma, se_w1, se_w2, out);
}

// round 13
// speedup vs baseline: 2.0079x; 1.0176x over previous
#include <cuda_runtime.h>
#include <cuda_fp16.h>
#include <math_constants.h>
#include <cstdint>

#define B_ 8
#define C_ 128
#define N_ 2304
#define BM 64
#define BN 64
#define NTILE 18
#define LOG2E 1.4426950408889634f

// ---------------- attention smem strides (halfs) ----------------
#define SQh 136
#define SKh 136
#define SVh 72
#define OFF_Q 0
#define OFF_K (BM*SQh)                    // 8704
#define OFF_V (OFF_K + 2*BN*SKh)          // 26112
#define SMEM_HALFS (OFF_V + 3*C_*SVh)     // 53760 halfs = 107520 B

// ---------------- qkv smem strides (halfs) ----------------
#define SX 136
#define SW 136
#define ST 136
#define QOFF_X  0
#define QOFF_W0 (C_*SX)                   // 17408
#define QOFF_T  (QOFF_W0 + 3*C_*SW)       // 69632
#define QKV_SMEM_HALFS (QOFF_T + C_*ST)   // 87040 halfs = 174080 B

__device__ __half g_qh[B_*N_*C_];   // [b][n][c]  (q pre-scaled by log2e)
__device__ __half g_kh[B_*N_*C_];   // [b][n][c]
__device__ __half g_vh[B_*C_*N_];   // [b][c][n]
__device__ float  g_ypart[B_*NTILE*C_];

// ---------------------------------------------------------------------------
__device__ __forceinline__ void cpa16(uint32_t s, const void* g){
    asm volatile("cp.async.cg.shared.global [%0], [%1], 16;" :: "r"(s), "l"(g));
}
__device__ __forceinline__ void cp_commit(){ asm volatile("cp.async.commit_group;"); }
__device__ __forceinline__ void cp_wait1(){ asm volatile("cp.async.wait_group 1;"); }
__device__ __forceinline__ void cp_wait0(){ asm volatile("cp.async.wait_group 0;"); }

__device__ __forceinline__ void ldsm4(uint32_t& r0,uint32_t& r1,uint32_t& r2,uint32_t& r3,
                                      uint32_t a){
    asm volatile("ldmatrix.sync.aligned.m8n8.x4.shared.b16 {%0,%1,%2,%3}, [%4];"
        : "=r"(r0),"=r"(r1),"=r"(r2),"=r"(r3) : "r"(a));
}
__device__ __forceinline__ void ldsm4t(uint32_t& r0,uint32_t& r1,uint32_t& r2,uint32_t& r3,
                                       uint32_t a){
    asm volatile("ldmatrix.sync.aligned.m8n8.x4.trans.shared.b16 {%0,%1,%2,%3}, [%4];"
        : "=r"(r0),"=r"(r1),"=r"(r2),"=r"(r3) : "r"(a));
}
__device__ __forceinline__ void stsm4t(uint32_t a, uint32_t r0,uint32_t r1,uint32_t r2,uint32_t r3){
    asm volatile("stmatrix.sync.aligned.m8n8.x4.trans.shared.b16 [%0], {%1,%2,%3,%4};"
        :: "r"(a), "r"(r0), "r"(r1), "r"(r2), "r"(r3));
}
__device__ __forceinline__ void sts32(uint32_t a, uint32_t v){
    asm volatile("st.shared.b32 [%0], %1;" :: "r"(a), "r"(v));
}
__device__ __forceinline__ void mma16(float* d, uint32_t a0,uint32_t a1,uint32_t a2,uint32_t a3,
                                      uint32_t b0,uint32_t b1){
    asm volatile(
      "mma.sync.aligned.m16n8k16.row.col.f32.f16.f16.f32 "
      "{%0,%1,%2,%3}, {%4,%5,%6,%7}, {%8,%9}, {%0,%1,%2,%3};"
      : "+f"(d[0]), "+f"(d[1]), "+f"(d[2]), "+f"(d[3])
      : "r"(a0), "r"(a1), "r"(a2), "r"(a3), "r"(b0), "r"(b1));
}
__device__ __forceinline__ uint32_t h2u(__half2 h){ return *reinterpret_cast<uint32_t*>(&h); }
__device__ __forceinline__ float ex2f(float x){
    float y; asm("ex2.approx.f32 %0, %1;" : "=f"(y) : "f"(x)); return y;
}
__device__ __forceinline__ uint32_t ex2_h2(uint32_t u){
    uint32_t r; asm("ex2.approx.f16x2 %0, %1;" : "=r"(r) : "r"(u)); return r;
}

// S-phase: s = Q * K^T for one 64x64 tile (per-warp 16x64)
__device__ __forceinline__ void s_phase(float s[8][4], uint32_t aQ, uint32_t kB){
    #pragma unroll
    for (int nt = 0; nt < 8; nt++)
        #pragma unroll
        for (int r = 0; r < 4; r++) s[nt][r] = 0.f;
    #pragma unroll
    for (int kc = 0; kc < 8; kc++) {
        uint32_t a0,a1,a2,a3;
        ldsm4(a0,a1,a2,a3, aQ + 32u*kc);
        #pragma unroll
        for (int np = 0; np < 4; np++) {
            uint32_t b0,b1,b2,b3;
            ldsm4(b0,b1,b2,b3, kB + 2u*(np*16*SKh + kc*16));
            mma16(s[2*np],   a0,a1,a2,a3, b0,b1);
            mma16(s[2*np+1], a0,a1,a2,a3, b2,b3);
        }
    }
}

// ---------------------------------------------------------------------------
// QKV via fp16 tensor cores; x AND weights converted fp32->fp16 inline.
// grid (N/128, B), block 256 (8 warps). No prep kernel.
// ---------------------------------------------------------------------------
__global__ void __launch_bounds__(256, 1) qkv_mma_kernel(
    const float* __restrict__ x,
    const float* __restrict__ Wq,
    const float* __restrict__ bq,
    const float* __restrict__ Wk,
    const float* __restrict__ bk,
    const float* __restrict__ Wv,
    const float* __restrict__ bv)
{
    extern __shared__ __half smh[];
    uint32_t sb = (uint32_t)__cvta_generic_to_shared(smh);

    const int tid  = threadIdx.x;
    const int b    = blockIdx.y;
    const int n0   = blockIdx.x * 128;
    const int warp = tid >> 5, lane = tid & 31;
    const int quad = lane >> 2, qt = lane & 3;

    const float* xb = x + (size_t)b * C_ * N_;

    // ---- x tile [c][n]: fp32 load + convert + smem store ----
    #pragma unroll
    for (int c2 = 0; c2 < 8; c2++) {
        int ch = tid + c2*256;
        int c = ch >> 4, nb = ch & 15;
        const float* src = xb + (size_t)c*N_ + n0 + nb*8;
        float4 v0 = *(const float4*)src;
        float4 v1 = *(const float4*)(src + 4);
        uint4 hv;
        hv.x = h2u(__floats2half2_rn(v0.x, v0.y));
        hv.y = h2u(__floats2half2_rn(v0.z, v0.w));
        hv.z = h2u(__floats2half2_rn(v1.x, v1.y));
        hv.w = h2u(__floats2half2_rn(v1.z, v1.w));
        *(uint4*)&smh[QOFF_X + c*SX + nb*8] = hv;
    }

    // ---- W0/W1/W2: fp32 load (L2-hot) + convert + smem store ----
    #pragma unroll
    for (int wi = 0; wi < 3; wi++) {
        const float* Wm = (wi == 0) ? Wq : (wi == 1) ? Wk : Wv;
        #pragma unroll
        for (int c2 = 0; c2 < 8; c2++) {
            int ch = tid + c2*256;
            int o = ch >> 4, cb = ch & 15;
            const float* src = Wm + o*C_ + cb*8;
            float4 v0 = *(const float4*)src;
            float4 v1 = *(const float4*)(src + 4);
            uint4 hv;
            hv.x = h2u(__floats2half2_rn(v0.x, v0.y));
            hv.y = h2u(__floats2half2_rn(v0.z, v0.w));
            hv.z = h2u(__floats2half2_rn(v1.x, v1.y));
            hv.w = h2u(__floats2half2_rn(v1.z, v1.w));
            *(uint4*)&smh[QOFF_W0 + wi*C_*SW + o*SW + cb*8] = hv;
        }
    }
    __syncthreads();

    // ---- SE partial: per-channel sum of this x tile ----
    if (tid < C_) {
        const uint4* row = (const uint4*)&smh[QOFF_X + tid*SX];
        float s = 0.f;
        #pragma unroll
        for (int u = 0; u < 16; u++) {
            uint4 v = row[u];
            float2 f0 = __half22float2(*(__half2*)&v.x);
            float2 f1 = __half22float2(*(__half2*)&v.y);
            float2 f2 = __half22float2(*(__half2*)&v.z);
            float2 f3 = __half22float2(*(__half2*)&v.w);
            s += (f0.x + f0.y) + (f1.x + f1.y) + (f2.x + f2.y) + (f3.x + f3.y);
        }
        g_ypart[((size_t)b*NTILE + blockIdx.x)*C_ + tid] = s;
    }

    const int r16 = lane & 15;
    const int hi8 = (lane >> 4) * 8;
    const uint32_t bX = sb + 2u*(QOFF_X + r16*SX + hi8);
    const int smm = lane >> 3, smr = lane & 7;
    const uint32_t stb = sb + 2u*(QOFF_T + ((smm>>1)*8 + smr)*ST + warp*16 + (smm&1)*8);
    const uint32_t tst0 = sb + 2u*(QOFF_T + (warp*16 + quad)*ST + qt*2);
    const uint32_t tst1 = tst0 + 2u*8*ST;

    const int o_r0 = warp*16 + quad, o_r1 = o_r0 + 8;

    #pragma unroll
    for (int which = 0; which < 3; which++) {
        const uint32_t aW = sb + 2u*(QOFF_W0 + which*C_*SW + (warp*16 + r16)*SW + hi8);

        float acc[16][4];
        #pragma unroll
        for (int nt = 0; nt < 16; nt++)
            #pragma unroll
            for (int r = 0; r < 4; r++) acc[nt][r] = 0.f;

        #pragma unroll
        for (int kc = 0; kc < 8; kc++) {
            uint32_t a0,a1,a2,a3;
            ldsm4(a0,a1,a2,a3, aW + 32u*kc);
            #pragma unroll
            for (int nt16 = 0; nt16 < 8; nt16++) {
                uint32_t b0,b1,b2,b3;
                ldsm4t(b0,b1,b2,b3, bX + 2u*(kc*16*SX + nt16*16));
                mma16(acc[2*nt16],   a0,a1,a2,a3, b0,b1);
                mma16(acc[2*nt16+1], a0,a1,a2,a3, b2,b3);
            }
        }

        const float* bias = (which == 0) ? bq : (which == 1) ? bk : bv;
        const float sc = (which == 0) ? LOG2E : 1.0f;
        float b0f = bias[o_r0], b1f = bias[o_r1];

        if (which < 2) {
            #pragma unroll
            for (int nt16 = 0; nt16 < 8; nt16++) {
                uint32_t r0 = h2u(__floats2half2_rn((acc[2*nt16][0]+b0f)*sc,   (acc[2*nt16][1]+b0f)*sc));
                uint32_t r1 = h2u(__floats2half2_rn((acc[2*nt16][2]+b1f)*sc,   (acc[2*nt16][3]+b1f)*sc));
                uint32_t r2 = h2u(__floats2half2_rn((acc[2*nt16+1][0]+b0f)*sc, (acc[2*nt16+1][1]+b0f)*sc));
                uint32_t r3 = h2u(__floats2half2_rn((acc[2*nt16+1][2]+b1f)*sc, (acc[2*nt16+1][3]+b1f)*sc));
                stsm4t(stb + 2u*(nt16*16*ST), r0, r1, r2, r3);
            }
            __syncthreads();
            __half* dsth = (which == 0) ? g_qh : g_kh;
            #pragma unroll
            for (int c2 = 0; c2 < 8; c2++) {
                int ch = tid + c2*256;
                int n = ch >> 4, ob = ch & 15;
                uint4 v = *(uint4*)&smh[QOFF_T + n*ST + ob*8];
                *(uint4*)(dsth + ((size_t)b*N_ + n0 + n)*C_ + ob*8) = v;
            }
            __syncthreads();
        } else {
            #pragma unroll
            for (int nt = 0; nt < 16; nt++) {
                sts32(tst0 + 16u*nt, h2u(__floats2half2_rn(acc[nt][0] + b0f, acc[nt][1] + b0f)));
                sts32(tst1 + 16u*nt, h2u(__floats2half2_rn(acc[nt][2] + b1f, acc[nt][3] + b1f)));
            }
            __syncthreads();
            #pragma unroll
            for (int c2 = 0; c2 < 8; c2++) {
                int ch = tid + c2*256;
                int o = ch >> 4, nb = ch & 15;
                uint4 v = *(uint4*)&smh[QOFF_T + o*ST + nb*8];
                *(uint4*)(g_vh + ((size_t)b*C_ + o)*N_ + n0 + nb*8) = v;
            }
        }
    }
}

// ---------------------------------------------------------------------------
// Flash attention (unchanged from best R12 config):
// MUFU-halved softmax via ex2.approx.f16x2, P in A-fragment registers,
// S(t+1) pipelined, K double / V triple buffered, in-CTA SE MLP.
// grid (N/64, B), block 128, 2 CTAs/SM.
// ---------------------------------------------------------------------------
__global__ void __launch_bounds__(128, 2) attn_kernel(
    const float* __restrict__ x,
    const float* __restrict__ gamma,
    const float* __restrict__ w1,
    const float* __restrict__ w2,
    float* __restrict__ out)
{
    extern __shared__ __half smh[];
    uint32_t sb = (uint32_t)__cvta_generic_to_shared(smh);
    __shared__ float ym[C_];
    __shared__ float y1_sh[8];
    __shared__ float se_sh[C_];

    const int tid  = threadIdx.x;
    const int b    = blockIdx.y;
    const int i0   = blockIdx.x * BM;
    const int warp = tid >> 5, lane = tid & 31;
    const int quad = lane >> 2, qt = lane & 3;

    const size_t bcn = (size_t)b * C_ * N_;
    const __half* qb = g_qh + (size_t)b * N_ * C_;
    const __half* kb = g_kh + (size_t)b * N_ * C_;
    const __half* vb = g_vh + (size_t)b * C_ * N_;

    // ---- prologue: G0 = (Q, K0, V0); G1 = (K1, V1) ----
    #pragma unroll
    for (int c2 = 0; c2 < 8; c2++) {
        int ch = tid + c2*128;
        int i = ch >> 4, cb = ch & 15;
        cpa16(sb + 2u*(OFF_Q + i*SQh + cb*8), qb + (size_t)(i0 + i)*C_ + cb*8);
    }
    #pragma unroll
    for (int c2 = 0; c2 < 8; c2++) {
        int ch = tid + c2*128;
        int j = ch >> 4, cb = ch & 15;
        cpa16(sb + 2u*(OFF_K + j*SKh + cb*8), kb + (size_t)j*C_ + cb*8);
    }
    #pragma unroll
    for (int c2 = 0; c2 < 8; c2++) {
        int ch = tid + c2*128;
        int c = ch >> 3, cb = ch & 7;
        cpa16(sb + 2u*(OFF_V + c*SVh + cb*8), vb + (size_t)c*N_ + cb*8);
    }
    cp_commit();
    #pragma unroll
    for (int c2 = 0; c2 < 8; c2++) {
        int ch = tid + c2*128;
        int j = ch >> 4, cb = ch & 15;
        cpa16(sb + 2u*(OFF_K + BN*SKh + j*SKh + cb*8), kb + (size_t)(BN + j)*C_ + cb*8);
    }
    #pragma unroll
    for (int c2 = 0; c2 < 8; c2++) {
        int ch = tid + c2*128;
        int c = ch >> 3, cb = ch & 7;
        cpa16(sb + 2u*(OFF_V + C_*SVh + c*SVh + cb*8), vb + (size_t)c*N_ + BN + cb*8);
    }
    cp_commit();

    // ---- SE MLP (overlapped with prologue cp.async) ----
    {
        float acc = 0.f;
        #pragma unroll
        for (int tt = 0; tt < NTILE; tt++)
            acc += g_ypart[((size_t)b*NTILE + tt)*C_ + tid];
        ym[tid] = acc * (1.f / (float)N_);
    }
    __syncthreads();
    {
        int h = tid >> 4, cl = tid & 15;
        float p = 0.f;
        #pragma unroll
        for (int u = 0; u < 8; u++) {
            int c = cl + u*16;
            p += w1[h*C_ + c] * ym[c];
        }
        #pragma unroll
        for (int off = 1; off < 16; off <<= 1)
            p += __shfl_xor_sync(0xffffffffu, p, off);
        if (cl == 0) y1_sh[h] = fmaxf(p, 0.f);
    }
    __syncthreads();
    {
        float a = 0.f;
        #pragma unroll
        for (int r = 0; r < 8; r++) a += w2[tid*8 + r] * y1_sh[r];
        se_sh[tid] = 1.f / (1.f + ex2f(-a * LOG2E));
    }

    cp_wait1();
    __syncthreads();

    float o[16][4];
    #pragma unroll
    for (int ct = 0; ct < 16; ct++)
        #pragma unroll
        for (int r = 0; r < 4; r++) o[ct][r] = 0.f;
    float m0 = -CUDART_INF_F, m1 = -CUDART_INF_F, l0 = 0.f, l1 = 0.f;

    const int r16  = lane & 15;
    const int ahi  = (lane >> 4) * 8;
    const int brow = (lane & 7) + ((lane >> 4) & 1) * 8;
    const int bcol = ((lane >> 3) & 1) * 8;

    const uint32_t aQ = sb + 2u*(OFF_Q + (warp*16 + r16)*SQh + ahi);

    // ---- S(0) ----
    float s[8][4];
    s_phase(s, aQ, sb + 2u*(OFF_K + brow*SKh + bcol));

    int vcur = 0, vnext2 = 2;
    for (int t = 0; t < 36; t++) {
        // ---- 1. softmax(t): half2 exponentials ----
        float mt0 = -CUDART_INF_F, mt1 = -CUDART_INF_F;
        #pragma unroll
        for (int nt = 0; nt < 8; nt++) {
            mt0 = fmaxf(mt0, fmaxf(s[nt][0], s[nt][1]));
            mt1 = fmaxf(mt1, fmaxf(s[nt][2], s[nt][3]));
        }
        #pragma unroll
        for (int off = 1; off < 4; off <<= 1) {
            mt0 = fmaxf(mt0, __shfl_xor_sync(0xffffffffu, mt0, off));
            mt1 = fmaxf(mt1, __shfl_xor_sync(0xffffffffu, mt1, off));
        }
        float mn0 = fmaxf(m0, mt0), mn1 = fmaxf(m1, mt1);
        float cor0 = ex2f(m0 - mn0), cor1 = ex2f(m1 - mn1);
        float rs0 = 0.f, rs1 = 0.f;
        uint32_t pa0[8], pa1[8];
        #pragma unroll
        for (int nt = 0; nt < 8; nt++) {
            pa0[nt] = ex2_h2(h2u(__floats2half2_rn(s[nt][0] - mn0, s[nt][1] - mn0)));
            pa1[nt] = ex2_h2(h2u(__floats2half2_rn(s[nt][2] - mn1, s[nt][3] - mn1)));
            float2 f0 = __half22float2(*(__half2*)&pa0[nt]);
            float2 f1 = __half22float2(*(__half2*)&pa1[nt]);
            rs0 += f0.x + f0.y;
            rs1 += f1.x + f1.y;
        }
        l0 = l0 * cor0 + rs0; m0 = mn0;
        l1 = l1 * cor1 + rs1; m1 = mn1;

        bool need = (cor0 != 1.f) | (cor1 != 1.f);
        if (__any_sync(0xffffffffu, need)) {
            #pragma unroll
            for (int ct = 0; ct < 16; ct++) {
                o[ct][0] *= cor0; o[ct][1] *= cor0;
                o[ct][2] *= cor1; o[ct][3] *= cor1;
            }
        }

        // ---- 2. K(t+1)/V(t+1) resident ----
        cp_wait0();
        __syncthreads();

        // ---- 3. stage K(t+2), V(t+2) ----
        if (t <= 33) {
            const int jn = (t + 2) * BN;
            const uint32_t kdst = sb + 2u*(OFF_K + (t & 1)*BN*SKh);
            const uint32_t vdst = sb + 2u*(OFF_V + vnext2*C_*SVh);
            #pragma unroll
            for (int c2 = 0; c2 < 8; c2++) {
                int ch = tid + c2*128;
                int j = ch >> 4, cb = ch & 15;
                cpa16(kdst + 2u*(j*SKh + cb*8), kb + (size_t)(jn + j)*C_ + cb*8);
            }
            #pragma unroll
            for (int c2 = 0; c2 < 8; c2++) {
                int ch = tid + c2*128;
                int c = ch >> 3, cb = ch & 7;
                cpa16(vdst + 2u*(c*SVh + cb*8), vb + (size_t)c*N_ + jn + cb*8);
            }
            cp_commit();
        }

        // ---- 4. S(t+1) ----
        if (t < 35)
            s_phase(s, aQ, sb + 2u*(OFF_K + ((t+1)&1)*BN*SKh + brow*SKh + bcol));

        // ---- 5. PV(t) ----
        const uint32_t vB = sb + 2u*(OFF_V + vcur*C_*SVh + brow*SVh + bcol);
        #pragma unroll
        for (int kc = 0; kc < 4; kc++) {
            uint32_t a0 = pa0[2*kc],   a1 = pa1[2*kc];
            uint32_t a2 = pa0[2*kc+1], a3 = pa1[2*kc+1];
            #pragma unroll
            for (int np = 0; np < 8; np++) {
                uint32_t b0,b1,b2,b3;
                ldsm4(b0,b1,b2,b3, vB + 2u*(np*16*SVh + kc*16));
                mma16(o[2*np],   a0,a1,a2,a3, b0,b1);
                mma16(o[2*np+1], a0,a1,a2,a3, b2,b3);
            }
        }

        vcur   = (vcur   == 2) ? 0 : vcur + 1;
        vnext2 = (vnext2 == 2) ? 0 : vnext2 + 1;
    }

    // ---- epilogue ----
    #pragma unroll
    for (int off = 1; off < 4; off <<= 1) {
        l0 += __shfl_xor_sync(0xffffffffu, l0, off);
        l1 += __shfl_xor_sync(0xffffffffu, l1, off);
    }
    const float gam = gamma[0];
    const float inv0 = 1.f / l0, inv1 = 1.f / l1;
    const int ir0 = i0 + warp*16 + quad, ir1 = ir0 + 8;
    #pragma unroll
    for (int ct = 0; ct < 16; ct++) {
        int c0 = ct*8 + qt*2;
        float se0 = se_sh[c0], se1 = se_sh[c0 + 1];
        size_t base0 = bcn + (size_t)c0 * N_;
        size_t base1 = base0 + N_;
        out[base0 + ir0] = gam * o[ct][0] * inv0 + x[base0 + ir0] * se0;
        out[base1 + ir0] = gam * o[ct][1] * inv0 + x[base1 + ir0] * se1;
        out[base0 + ir1] = gam * o[ct][2] * inv1 + x[base0 + ir1] * se0;
        out[base1 + ir1] = gam * o[ct][3] * inv1 + x[base1 + ir1] * se1;
    }
}

// ---------------------------------------------------------------------------
extern "C" void kernel_launch(void* const* d_in, const int* in_sizes, int n_in,
                              void* d_out, int out_size)
{
    const float* x     = (const float*)d_in[0];
    const float* Wq    = (const float*)d_in[1];
    const float* bq    = (const float*)d_in[2];
    const float* Wk    = (const float*)d_in[3];
    const float* bk    = (const float*)d_in[4];
    const float* Wv    = (const float*)d_in[5];
    const float* bv    = (const float*)d_in[6];
    const float* se_w1 = (const float*)d_in[7];
    const float* se_w2 = (const float*)d_in[8];
    const float* gamma = (const float*)d_in[9];
    float* out = (float*)d_out;

    static int smem_set = 0;
    if (!smem_set) {
        cudaFuncSetAttribute(attn_kernel,
                             cudaFuncAttributeMaxDynamicSharedMemorySize,
                             SMEM_HALFS * (int)sizeof(__half));
        cudaFuncSetAttribute(qkv_mma_kernel,
                             cudaFuncAttributeMaxDynamicSharedMemorySize,
                             QKV_SMEM_HALFS * (int)sizeof(__half));
        smem_set = 1;
    }

    qkv_mma_kernel<<<dim3(N_/128, B_), 256, QKV_SMEM_HALFS * sizeof(__half)>>>(
        x, Wq, bq, Wk, bk, Wv, bv);
    attn_kernel<<<dim3(N_/BM, B_), 128, SMEM_HALFS * sizeof(__half)>>>(
        x, gamma, se_w1, se_w2, out);
}